// round 2
// baseline (speedup 1.0000x reference)
#include <cuda_runtime.h>
#include <math.h>

#define BQ 4096      // batch rows
#define SN 8192      // samples
#define DX 256
#define DY 128
#define NSPLIT 2     // S-dimension split across CTAs
#define BM 64
#define BN 64
#define BK 32
#define NTHREADS 256

// ---------------- device scratch (no allocations allowed) ----------------
__device__ float g_x2[BQ];
__device__ float g_y2[BQ];
__device__ float g_xs2[SN];
__device__ float g_ys2[SN];
// partial LSE state per (term, row, split): m and s
__device__ float g_pm[3 * BQ * NSPLIT];
__device__ float g_ps[3 * BQ * NSPLIT];

// ---------------- norms: one warp per row ----------------
__global__ void norms_kernel(const float* __restrict__ x, const float* __restrict__ y,
                             const float* __restrict__ xs, const float* __restrict__ ys) {
    int warp = (blockIdx.x * blockDim.x + threadIdx.x) >> 5;
    int lane = threadIdx.x & 31;
    const float* src; int dim; float* dst; int row;
    if (warp < BQ)            { src = x;  dim = DX; dst = g_x2;  row = warp; }
    else if (warp < 2*BQ)     { src = y;  dim = DY; dst = g_y2;  row = warp - BQ; }
    else if (warp < 2*BQ+SN)  { src = xs; dim = DX; dst = g_xs2; row = warp - 2*BQ; }
    else                      { src = ys; dim = DY; dst = g_ys2; row = warp - 2*BQ - SN; }
    const float4* p = (const float4*)(src + (size_t)row * dim);
    float s = 0.f;
    for (int i = lane; i < dim/4; i += 32) {
        float4 v = p[i];
        s += v.x*v.x + v.y*v.y + v.z*v.z + v.w*v.w;
    }
    #pragma unroll
    for (int o = 16; o; o >>= 1) s += __shfl_xor_sync(0xffffffffu, s, o);
    if (lane == 0) dst[row] = s;
}

// online LSE update: mostly 1 exp per element
__device__ __forceinline__ void upd(float& m, float& s, float e) {
    if (e <= m) {
        s += __expf(e - m);
    } else {
        s = s * __expf(m - e) + 1.f;
        m = e;
    }
}

// load 64x32 tile (rows x k) transposed into dst[k][row], row-major src
__device__ __forceinline__ void load_tile(float (*dst)[68], const float* __restrict__ src,
                                          int ld, int kc, int tid) {
    #pragma unroll
    for (int i = 0; i < 2; i++) {
        int f  = tid + i * NTHREADS;   // 0..511
        int r  = f >> 3;               // 0..63
        int kv = f & 7;                // 0..7 (float4 within 32-wide k chunk)
        float4 v = *(const float4*)(src + (size_t)r * ld + kc + kv * 4);
        dst[kv*4+0][r] = v.x;
        dst[kv*4+1][r] = v.y;
        dst[kv*4+2][r] = v.z;
        dst[kv*4+3][r] = v.w;
    }
}

__global__ __launch_bounds__(NTHREADS)
void mi_main(const float* __restrict__ x, const float* __restrict__ y,
             const float* __restrict__ xs, const float* __restrict__ ys) {
    __shared__ union {
        struct { float As[BK][68]; float Bs[BK][68]; } t;
        float red[3][BM][17][2];
    } sm;

    const int row0  = blockIdx.x * BM;
    const int split = blockIdx.y;
    const int s_beg = split * (SN / NSPLIT);
    const int s_end = s_beg + (SN / NSPLIT);
    const int tid = threadIdx.x;
    const int tx  = tid & 15;   // col group
    const int ty  = tid >> 4;   // row group

    float x2r[4], y2r[4];
    #pragma unroll
    for (int i = 0; i < 4; i++) {
        x2r[i] = g_x2[row0 + ty*4 + i];
        y2r[i] = g_y2[row0 + ty*4 + i];
    }

    float mX[4], sX[4], mY[4], sY[4], mZ[4], sZ[4];
    #pragma unroll
    for (int i = 0; i < 4; i++) {
        mX[i] = mY[i] = mZ[i] = -1e30f;
        sX[i] = sY[i] = sZ[i] = 0.f;
    }

    for (int c0 = s_beg; c0 < s_end; c0 += BN) {
        float ax[4][4], ay[4][4];
        #pragma unroll
        for (int i = 0; i < 4; i++)
            #pragma unroll
            for (int j = 0; j < 4; j++) { ax[i][j] = 0.f; ay[i][j] = 0.f; }

        // ---- X GEMM chunk loop (K = 256) ----
        for (int kc = 0; kc < DX; kc += BK) {
            __syncthreads();
            load_tile(sm.t.As, x  + (size_t)row0 * DX, DX, kc, tid);
            load_tile(sm.t.Bs, xs + (size_t)c0   * DX, DX, kc, tid);
            __syncthreads();
            #pragma unroll
            for (int kk = 0; kk < BK; kk++) {
                float4 av = *(const float4*)&sm.t.As[kk][ty*4];
                float4 bv = *(const float4*)&sm.t.Bs[kk][tx*4];
                float a[4] = {av.x, av.y, av.z, av.w};
                float b[4] = {bv.x, bv.y, bv.z, bv.w};
                #pragma unroll
                for (int i = 0; i < 4; i++)
                    #pragma unroll
                    for (int j = 0; j < 4; j++)
                        ax[i][j] = fmaf(a[i], b[j], ax[i][j]);
            }
        }
        // ---- Y GEMM chunk loop (K = 128) ----
        for (int kc = 0; kc < DY; kc += BK) {
            __syncthreads();
            load_tile(sm.t.As, y  + (size_t)row0 * DY, DY, kc, tid);
            load_tile(sm.t.Bs, ys + (size_t)c0   * DY, DY, kc, tid);
            __syncthreads();
            #pragma unroll
            for (int kk = 0; kk < BK; kk++) {
                float4 av = *(const float4*)&sm.t.As[kk][ty*4];
                float4 bv = *(const float4*)&sm.t.Bs[kk][tx*4];
                float a[4] = {av.x, av.y, av.z, av.w};
                float b[4] = {bv.x, bv.y, bv.z, bv.w};
                #pragma unroll
                for (int i = 0; i < 4; i++)
                    #pragma unroll
                    for (int j = 0; j < 4; j++)
                        ay[i][j] = fmaf(a[i], b[j], ay[i][j]);
            }
        }

        // ---- fold tile into online LSEs ----
        float c2x[4], c2y[4];
        #pragma unroll
        for (int j = 0; j < 4; j++) {
            c2x[j] = g_xs2[c0 + tx*4 + j];
            c2y[j] = g_ys2[c0 + tx*4 + j];
        }
        #pragma unroll
        for (int i = 0; i < 4; i++) {
            #pragma unroll
            for (int j = 0; j < 4; j++) {
                // ex = -0.5*(x2 + xs2 - 2*dot) = dot - 0.5*(x2+xs2)
                float ex = ax[i][j] - 0.5f * (x2r[i] + c2x[j]);
                float ey = ay[i][j] - 0.5f * (y2r[i] + c2y[j]);
                float ez = ex + ey;
                upd(mX[i], sX[i], ex);
                upd(mY[i], sY[i], ey);
                upd(mZ[i], sZ[i], ez);
            }
        }
    }

    // ---- merge across the 16 tx threads sharing each row ----
    __syncthreads();
    #pragma unroll
    for (int i = 0; i < 4; i++) {
        int r = ty*4 + i;
        sm.red[0][r][tx][0] = mX[i]; sm.red[0][r][tx][1] = sX[i];
        sm.red[1][r][tx][0] = mY[i]; sm.red[1][r][tx][1] = sY[i];
        sm.red[2][r][tx][0] = mZ[i]; sm.red[2][r][tx][1] = sZ[i];
    }
    __syncthreads();
    if (tid < 192) {
        int t = tid >> 6, r = tid & 63;
        float M = -1e30f;
        #pragma unroll
        for (int k = 0; k < 16; k++) M = fmaxf(M, sm.red[t][r][k][0]);
        float S = 0.f;
        #pragma unroll
        for (int k = 0; k < 16; k++) S += sm.red[t][r][k][1] * __expf(sm.red[t][r][k][0] - M);
        int g = (t * BQ + row0 + r) * NSPLIT + split;
        g_pm[g] = M;
        g_ps[g] = S;
    }
}

// ---------------- finalize: merge splits, compute mean ----------------
__global__ void finalize_kernel(float* __restrict__ out) {
    __shared__ float acc[256];
    float local = 0.f;
    for (int r = threadIdx.x; r < BQ; r += 256) {
        float lse[3];
        #pragma unroll
        for (int t = 0; t < 3; t++) {
            int base = (t * BQ + r) * NSPLIT;
            float M = -1e30f;
            #pragma unroll
            for (int sp = 0; sp < NSPLIT; sp++) M = fmaxf(M, g_pm[base + sp]);
            float S = 0.f;
            #pragma unroll
            for (int sp = 0; sp < NSPLIT; sp++) S += g_ps[base + sp] * __expf(g_pm[base + sp] - M);
            lse[t] = M + logf(S);
        }
        local += lse[2] - lse[0] - lse[1];
    }
    acc[threadIdx.x] = local;
    __syncthreads();
    #pragma unroll
    for (int o = 128; o; o >>= 1) {
        if (threadIdx.x < o) acc[threadIdx.x] += acc[threadIdx.x + o];
        __syncthreads();
    }
    if (threadIdx.x == 0) out[0] = acc[0] / (float)BQ;
}

extern "C" void kernel_launch(void* const* d_in, const int* in_sizes, int n_in,
                              void* d_out, int out_size) {
    (void)in_sizes; (void)n_in; (void)out_size;
    const float* x  = (const float*)d_in[0];
    const float* y  = (const float*)d_in[1];
    const float* xs = (const float*)d_in[2];
    const float* ys = (const float*)d_in[3];

    // 24576 rows total, one warp per row, 8 warps per block
    norms_kernel<<<(2*BQ + 2*SN) / 8, 256>>>(x, y, xs, ys);

    dim3 grid(BQ / BM, NSPLIT);
    mi_main<<<grid, NTHREADS>>>(x, y, xs, ys);

    finalize_kernel<<<1, 256>>>((float*)d_out);
}

// round 3
// speedup vs baseline: 1.5895x; 1.5895x over previous
#include <cuda_runtime.h>
#include <math.h>

#define BQ 4096      // batch rows
#define SN 8192      // samples
#define DX 256
#define DY 128
#define NSPLIT 4     // S-dimension split across CTAs
#define BM 64
#define BN 128
#define BK 32
#define NTHREADS 128
#define SA 96        // As smem stride (floats), multiple of 32
#define SB 160       // Bs smem stride (floats), multiple of 32

typedef unsigned long long u64;

// ---------------- device scratch ----------------
__device__ float g_x2[BQ];
__device__ float g_y2[BQ];
__device__ float g_xs2[SN];
__device__ float g_ys2[SN];
__device__ float g_pm[3 * BQ * NSPLIT];
__device__ float g_ps[3 * BQ * NSPLIT];

// ---------------- packed f32x2 helpers ----------------
__device__ __forceinline__ u64 pack2(float a, float b) {
    u64 r; asm("mov.b64 %0, {%1,%2};" : "=l"(r) : "f"(a), "f"(b)); return r;
}
__device__ __forceinline__ float2 unpack2(u64 v) {
    float2 r; asm("mov.b64 {%0,%1}, %2;" : "=f"(r.x), "=f"(r.y) : "l"(v)); return r;
}
__device__ __forceinline__ void ffma2(u64& d, u64 a, u64 b) {
    asm("fma.rn.f32x2 %0, %1, %2, %0;" : "+l"(d) : "l"(a), "l"(b));
}

// ---------------- norms: one warp per row ----------------
__global__ void norms_kernel(const float* __restrict__ x, const float* __restrict__ y,
                             const float* __restrict__ xs, const float* __restrict__ ys) {
    int warp = (blockIdx.x * blockDim.x + threadIdx.x) >> 5;
    int lane = threadIdx.x & 31;
    const float* src; int dim; float* dst; int row;
    if (warp < BQ)            { src = x;  dim = DX; dst = g_x2;  row = warp; }
    else if (warp < 2*BQ)     { src = y;  dim = DY; dst = g_y2;  row = warp - BQ; }
    else if (warp < 2*BQ+SN)  { src = xs; dim = DX; dst = g_xs2; row = warp - 2*BQ; }
    else                      { src = ys; dim = DY; dst = g_ys2; row = warp - 2*BQ - SN; }
    const float4* p = (const float4*)(src + (size_t)row * dim);
    float s = 0.f;
    for (int i = lane; i < dim/4; i += 32) {
        float4 v = p[i];
        s += v.x*v.x + v.y*v.y + v.z*v.z + v.w*v.w;
    }
    #pragma unroll
    for (int o = 16; o; o >>= 1) s += __shfl_xor_sync(0xffffffffu, s, o);
    if (lane == 0) dst[row] = s;
}

// branchless online LSE update: exactly 1 MUFU exp, predicated select
__device__ __forceinline__ void upd(float& m, float& s, float e) {
    float d = e - m;
    float t = __expf(-fabsf(d));     // exp(e-m) if d<=0 else exp(m-e)
    if (d <= 0.f) { s += t; }
    else          { s = fmaf(s, t, 1.f); m = e; }
}

// smem k-major layout with per-row shift: addr(kk, col) = kk*S + ((kk>>2)<<2) + col
// Transposed STS is bank-conflict-free: bank = 4*kv + r covers all 32 banks.
__device__ __forceinline__ int krow(int kk, int S) { return kk * S + ((kk >> 2) << 2); }

__device__ __forceinline__ void load_tile(float* __restrict__ dst, int S,
                                          const float* __restrict__ src, int ld,
                                          int kc, int nrows, int tid) {
    int total = nrows * (BK / 4);          // float4 count
    for (int f = tid; f < total; f += NTHREADS) {
        int r  = f >> 3;                   // row
        int kv = f & 7;                    // float4 index within 32-k chunk
        float4 v = *(const float4*)(src + (size_t)r * ld + kc + kv * 4);
        float* base = dst + (kv * 4) * S + kv * 4 + r;
        base[0]     = v.x;
        base[S]     = v.y;
        base[2 * S] = v.z;
        base[3 * S] = v.w;
    }
}

__global__ __launch_bounds__(NTHREADS, 2)
void mi_main(const float* __restrict__ x, const float* __restrict__ y,
             const float* __restrict__ xs, const float* __restrict__ ys) {
    __shared__ union {
        struct { float As[BK * SA]; float Bs[BK * SB]; } t;
        float red[3][BM][16][2];
    } sm;

    const int row0  = blockIdx.x * BM;
    const int split = blockIdx.y;
    const int s_beg = split * (SN / NSPLIT);
    const int tid = threadIdx.x;
    const int tx  = tid & 15;    // col group: j = tx*8 + jj  (BN = 128)
    const int ty  = tid >> 4;    // row group: i = ty*8 + ii  (BM = 64)

    // preload -0.5 * row norms
    float bxi[8], byi[8];
    #pragma unroll
    for (int i = 0; i < 8; i++) {
        bxi[i] = -0.5f * g_x2[row0 + ty*8 + i];
        byi[i] = -0.5f * g_y2[row0 + ty*8 + i];
    }

    float mX[8], sX[8], mY[8], sY[8], mZ[8], sZ[8];
    #pragma unroll
    for (int i = 0; i < 8; i++) {
        mX[i] = mY[i] = mZ[i] = -1e30f;
        sX[i] = sY[i] = sZ[i] = 0.f;
    }

    for (int t0 = 0; t0 < (SN / NSPLIT) / BN; t0++) {
        const int c0 = s_beg + t0 * BN;
        u64 ax[8][4], ay[8][4];
        #pragma unroll
        for (int i = 0; i < 8; i++)
            #pragma unroll
            for (int j = 0; j < 4; j++) { ax[i][j] = 0ull; ay[i][j] = 0ull; }

        // ---- X GEMM (K = 256) ----
        for (int kc = 0; kc < DX; kc += BK) {
            __syncthreads();
            load_tile(sm.t.As, SA, x  + (size_t)row0 * DX, DX, kc, BM, tid);
            load_tile(sm.t.Bs, SB, xs + (size_t)c0   * DX, DX, kc, BN, tid);
            __syncthreads();
            #pragma unroll 8
            for (int kk = 0; kk < BK; kk++) {
                const float* ap = sm.t.As + krow(kk, SA) + ty * 8;
                const float* bp = sm.t.Bs + krow(kk, SB) + tx * 8;
                float4 a0 = *(const float4*)(ap);
                float4 a1 = *(const float4*)(ap + 4);
                u64 b0 = *(const u64*)(bp);
                u64 b1 = *(const u64*)(bp + 2);
                u64 b2 = *(const u64*)(bp + 4);
                u64 b3 = *(const u64*)(bp + 6);
                float av[8] = {a0.x,a0.y,a0.z,a0.w,a1.x,a1.y,a1.z,a1.w};
                #pragma unroll
                for (int i = 0; i < 8; i++) {
                    u64 ad = pack2(av[i], av[i]);
                    ffma2(ax[i][0], ad, b0);
                    ffma2(ax[i][1], ad, b1);
                    ffma2(ax[i][2], ad, b2);
                    ffma2(ax[i][3], ad, b3);
                }
            }
        }
        // ---- Y GEMM (K = 128) ----
        for (int kc = 0; kc < DY; kc += BK) {
            __syncthreads();
            load_tile(sm.t.As, SA, y  + (size_t)row0 * DY, DY, kc, BM, tid);
            load_tile(sm.t.Bs, SB, ys + (size_t)c0   * DY, DY, kc, BN, tid);
            __syncthreads();
            #pragma unroll 8
            for (int kk = 0; kk < BK; kk++) {
                const float* ap = sm.t.As + krow(kk, SA) + ty * 8;
                const float* bp = sm.t.Bs + krow(kk, SB) + tx * 8;
                float4 a0 = *(const float4*)(ap);
                float4 a1 = *(const float4*)(ap + 4);
                u64 b0 = *(const u64*)(bp);
                u64 b1 = *(const u64*)(bp + 2);
                u64 b2 = *(const u64*)(bp + 4);
                u64 b3 = *(const u64*)(bp + 6);
                float av[8] = {a0.x,a0.y,a0.z,a0.w,a1.x,a1.y,a1.z,a1.w};
                #pragma unroll
                for (int i = 0; i < 8; i++) {
                    u64 ad = pack2(av[i], av[i]);
                    ffma2(ay[i][0], ad, b0);
                    ffma2(ay[i][1], ad, b1);
                    ffma2(ay[i][2], ad, b2);
                    ffma2(ay[i][3], ad, b3);
                }
            }
        }

        // ---- fold tile into online LSEs ----
        float cxj[8], cyj[8];
        #pragma unroll
        for (int j = 0; j < 8; j++) {
            cxj[j] = -0.5f * g_xs2[c0 + tx*8 + j];
            cyj[j] = -0.5f * g_ys2[c0 + tx*8 + j];
        }
        #pragma unroll
        for (int i = 0; i < 8; i++) {
            #pragma unroll
            for (int jp = 0; jp < 4; jp++) {
                float2 dx = unpack2(ax[i][jp]);
                float2 dy = unpack2(ay[i][jp]);
                {
                    float ex = dx.x + (bxi[i] + cxj[2*jp]);
                    float ey = dy.x + (byi[i] + cyj[2*jp]);
                    float ez = ex + ey;
                    upd(mX[i], sX[i], ex);
                    upd(mY[i], sY[i], ey);
                    upd(mZ[i], sZ[i], ez);
                }
                {
                    float ex = dx.y + (bxi[i] + cxj[2*jp+1]);
                    float ey = dy.y + (byi[i] + cyj[2*jp+1]);
                    float ez = ex + ey;
                    upd(mX[i], sX[i], ex);
                    upd(mY[i], sY[i], ey);
                    upd(mZ[i], sZ[i], ez);
                }
            }
        }
    }

    // ---- merge across the 16 tx threads sharing each row ----
    __syncthreads();
    #pragma unroll
    for (int i = 0; i < 8; i++) {
        int r = ty*8 + i;
        sm.red[0][r][tx][0] = mX[i]; sm.red[0][r][tx][1] = sX[i];
        sm.red[1][r][tx][0] = mY[i]; sm.red[1][r][tx][1] = sY[i];
        sm.red[2][r][tx][0] = mZ[i]; sm.red[2][r][tx][1] = sZ[i];
    }
    __syncthreads();
    for (int task = tid; task < 3 * BM; task += NTHREADS) {
        int t = task / BM, r = task % BM;
        float M = -1e30f;
        #pragma unroll
        for (int k = 0; k < 16; k++) M = fmaxf(M, sm.red[t][r][k][0]);
        float S = 0.f;
        #pragma unroll
        for (int k = 0; k < 16; k++) S += sm.red[t][r][k][1] * __expf(sm.red[t][r][k][0] - M);
        int g = (t * BQ + row0 + r) * NSPLIT + split;
        g_pm[g] = M;
        g_ps[g] = S;
    }
}

// ---------------- finalize: merge splits, compute mean ----------------
__global__ void finalize_kernel(float* __restrict__ out) {
    __shared__ float acc[256];
    float local = 0.f;
    for (int r = threadIdx.x; r < BQ; r += 256) {
        float lse[3];
        #pragma unroll
        for (int t = 0; t < 3; t++) {
            int base = (t * BQ + r) * NSPLIT;
            float M = -1e30f;
            #pragma unroll
            for (int sp = 0; sp < NSPLIT; sp++) M = fmaxf(M, g_pm[base + sp]);
            float S = 0.f;
            #pragma unroll
            for (int sp = 0; sp < NSPLIT; sp++) S += g_ps[base + sp] * __expf(g_pm[base + sp] - M);
            lse[t] = M + logf(S);
        }
        local += lse[2] - lse[0] - lse[1];
    }
    acc[threadIdx.x] = local;
    __syncthreads();
    #pragma unroll
    for (int o = 128; o; o >>= 1) {
        if (threadIdx.x < o) acc[threadIdx.x] += acc[threadIdx.x + o];
        __syncthreads();
    }
    if (threadIdx.x == 0) out[0] = acc[0] / (float)BQ;
}

extern "C" void kernel_launch(void* const* d_in, const int* in_sizes, int n_in,
                              void* d_out, int out_size) {
    (void)in_sizes; (void)n_in; (void)out_size;
    const float* x  = (const float*)d_in[0];
    const float* y  = (const float*)d_in[1];
    const float* xs = (const float*)d_in[2];
    const float* ys = (const float*)d_in[3];

    norms_kernel<<<(2*BQ + 2*SN) / 8, 256>>>(x, y, xs, ys);

    dim3 grid(BQ / BM, NSPLIT);
    mi_main<<<grid, NTHREADS>>>(x, y, xs, ys);

    finalize_kernel<<<1, 256>>>((float*)d_out);
}

// round 8
// speedup vs baseline: 2.1384x; 1.3453x over previous
#include <cuda_runtime.h>
#include <cuda_bf16.h>
#include <cstdint>
#include <math.h>

#define BQ 4096
#define SN 8192
#define DX 256
#define DY 128
#define XK (3*DX)          // 768: [hi | hi | lo] x [hi | lo | hi]
#define YK (3*DY)          // 384
#define BM 128
#define BN 64
#define BKC 64             // bf16 k per chunk
#define NSPLIT 16
#define NTHREADS 256
#define NXCH (XK/BKC)      // 12
#define NYCH (YK/BKC)      // 6
#define NCH  (NXCH+NYCH)   // 18
#define NTILE ((SN/NSPLIT)/BN)  // 8
#define SROW 72            // smem row stride in bf16 (144 B) -> conflict-free frags
#define SROWB 144

// smem byte offsets: A bufs 128*144=18432 each, B bufs 64*144=9216 each
#define SMEM_A(b)  ((b)*18432)
#define SMEM_B(b)  (36864 + (b)*9216)
#define SMEM_BYTES 55296

// ---------------- device scratch ----------------
__device__ __nv_bfloat16 g_xa[BQ*XK];
__device__ __nv_bfloat16 g_xb[SN*XK];
__device__ __nv_bfloat16 g_ya[BQ*YK];
__device__ __nv_bfloat16 g_yb[SN*YK];
__device__ float g_x2[BQ], g_y2[BQ], g_xs2[SN], g_ys2[SN];
__device__ float g_pm[3*BQ*NSPLIT], g_ps[3*BQ*NSPLIT];

// ---------------- helpers ----------------
__device__ __forceinline__ uint32_t smem_u32(const void* p) {
    uint32_t a;
    asm("{ .reg .u64 t; cvta.to.shared.u64 t, %1; cvt.u32.u64 %0, t; }" : "=r"(a) : "l"(p));
    return a;
}
__device__ __forceinline__ void cp16(uint32_t s, const void* g) {
    asm volatile("cp.async.cg.shared.global [%0], [%1], 16;" :: "r"(s), "l"(g));
}
__device__ __forceinline__ void cp_commit() {
    asm volatile("cp.async.commit_group;" ::: "memory");
}
__device__ __forceinline__ void cp_wait1() {
    asm volatile("cp.async.wait_group 1;" ::: "memory");
}
__device__ __forceinline__ void cp_wait0() {
    asm volatile("cp.async.wait_group 0;" ::: "memory");
}

// branchless online LSE update: exactly 1 MUFU exp
__device__ __forceinline__ void upd(float& m, float& s, float e) {
    float d = e - m;
    float t = __expf(-fabsf(d));
    if (d <= 0.f) { s += t; }
    else          { s = fmaf(s, t, 1.f); m = e; }
}

// ---------------- prep: bf16 hi/lo split, K-concatenated ----------------
__global__ void prep_kernel(const float* __restrict__ x, const float* __restrict__ y,
                            const float* __restrict__ xs, const float* __restrict__ ys) {
    int i = blockIdx.x * blockDim.x + threadIdx.x;
    const int N1 = BQ*DX, N2 = SN*DX, N3 = BQ*DY, N4 = SN*DY;
    float v; __nv_bfloat16 h, l;
    if (i < N1) {
        v = x[i]; h = __float2bfloat16(v); l = __float2bfloat16(v - __bfloat162float(h));
        int m = i / DX, k = i % DX;
        g_xa[m*XK + k] = h; g_xa[m*XK + DX + k] = h; g_xa[m*XK + 2*DX + k] = l;
    } else if (i < N1 + N2) {
        int j = i - N1;
        v = xs[j]; h = __float2bfloat16(v); l = __float2bfloat16(v - __bfloat162float(h));
        int n = j / DX, k = j % DX;
        g_xb[n*XK + k] = h; g_xb[n*XK + DX + k] = l; g_xb[n*XK + 2*DX + k] = h;
    } else if (i < N1 + N2 + N3) {
        int j = i - N1 - N2;
        v = y[j]; h = __float2bfloat16(v); l = __float2bfloat16(v - __bfloat162float(h));
        int m = j / DY, k = j % DY;
        g_ya[m*YK + k] = h; g_ya[m*YK + DY + k] = h; g_ya[m*YK + 2*DY + k] = l;
    } else if (i < N1 + N2 + N3 + N4) {
        int j = i - N1 - N2 - N3;
        v = ys[j]; h = __float2bfloat16(v); l = __float2bfloat16(v - __bfloat162float(h));
        int n = j / DY, k = j % DY;
        g_yb[n*YK + k] = h; g_yb[n*YK + DY + k] = l; g_yb[n*YK + 2*DY + k] = h;
    }
}

// ---------------- norms: one warp per row (exact fp32) ----------------
__global__ void norms_kernel(const float* __restrict__ x, const float* __restrict__ y,
                             const float* __restrict__ xs, const float* __restrict__ ys) {
    int warp = (blockIdx.x * blockDim.x + threadIdx.x) >> 5;
    int lane = threadIdx.x & 31;
    const float* src; int dim; float* dst; int row;
    if (warp < BQ)            { src = x;  dim = DX; dst = g_x2;  row = warp; }
    else if (warp < 2*BQ)     { src = y;  dim = DY; dst = g_y2;  row = warp - BQ; }
    else if (warp < 2*BQ+SN)  { src = xs; dim = DX; dst = g_xs2; row = warp - 2*BQ; }
    else                      { src = ys; dim = DY; dst = g_ys2; row = warp - 2*BQ - SN; }
    const float4* p = (const float4*)(src + (size_t)row * dim);
    float s = 0.f;
    for (int i = lane; i < dim/4; i += 32) {
        float4 v = p[i];
        s += v.x*v.x + v.y*v.y + v.z*v.z + v.w*v.w;
    }
    #pragma unroll
    for (int o = 16; o; o >>= 1) s += __shfl_xor_sync(0xffffffffu, s, o);
    if (lane == 0) dst[row] = s;
}

// ---------------- chunk load via cp.async ----------------
__device__ __forceinline__ void issue_chunk(uint32_t sb, int buf, int c,
                                            int row0, int c0, int tid) {
    const __nv_bfloat16 *asrc, *bsrc; int ldk, k0;
    if (c < NXCH) {
        asrc = g_xa + (size_t)row0 * XK; bsrc = g_xb + (size_t)c0 * XK;
        ldk = XK; k0 = c * BKC;
    } else {
        asrc = g_ya + (size_t)row0 * YK; bsrc = g_yb + (size_t)c0 * YK;
        ldk = YK; k0 = (c - NXCH) * BKC;
    }
    uint32_t abase = sb + SMEM_A(buf), bbase = sb + SMEM_B(buf);
    #pragma unroll
    for (int i = 0; i < 4; i++) {
        int u = tid + i * NTHREADS;      // 0..1023
        int r = u >> 3, cv = u & 7;
        cp16(abase + r * SROWB + cv * 16, asrc + (size_t)r * ldk + k0 + cv * 8);
    }
    #pragma unroll
    for (int i = 0; i < 2; i++) {
        int u = tid + i * NTHREADS;      // 0..511
        int r = u >> 3, cv = u & 7;
        cp16(bbase + r * SROWB + cv * 16, bsrc + (size_t)r * ldk + k0 + cv * 8);
    }
    cp_commit();
}

// ---------------- warp mma over one 64-k chunk ----------------
__device__ __forceinline__ void mma_chunk(const __nv_bfloat16* __restrict__ As,
                                          const __nv_bfloat16* __restrict__ Bs,
                                          int wm, int wn, int g, int t,
                                          float (*d)[4][4]) {
    #pragma unroll
    for (int kk = 0; kk < 4; kk++) {
        int kc = kk * 16 + 2 * t;
        uint32_t a[2][4], b[4][2];
        #pragma unroll
        for (int mi = 0; mi < 2; mi++) {
            const __nv_bfloat16* base = As + (wm*32 + mi*16 + g) * SROW + kc;
            a[mi][0] = *(const uint32_t*)(base);
            a[mi][1] = *(const uint32_t*)(base + 8*SROW);
            a[mi][2] = *(const uint32_t*)(base + 8);
            a[mi][3] = *(const uint32_t*)(base + 8*SROW + 8);
        }
        #pragma unroll
        for (int ni = 0; ni < 4; ni++) {
            const __nv_bfloat16* base = Bs + (wn*32 + ni*8 + g) * SROW + kc;
            b[ni][0] = *(const uint32_t*)(base);
            b[ni][1] = *(const uint32_t*)(base + 8);
        }
        #pragma unroll
        for (int mi = 0; mi < 2; mi++)
            #pragma unroll
            for (int ni = 0; ni < 4; ni++)
                asm volatile(
                    "mma.sync.aligned.m16n8k16.row.col.f32.bf16.bf16.f32 "
                    "{%0,%1,%2,%3}, {%4,%5,%6,%7}, {%8,%9}, {%0,%1,%2,%3};"
                    : "+f"(d[mi][ni][0]), "+f"(d[mi][ni][1]),
                      "+f"(d[mi][ni][2]), "+f"(d[mi][ni][3])
                    : "r"(a[mi][0]), "r"(a[mi][1]), "r"(a[mi][2]), "r"(a[mi][3]),
                      "r"(b[ni][0]), "r"(b[ni][1]));
    }
}

extern __shared__ char dynsmem[];

__global__ __launch_bounds__(NTHREADS, 2)
void mi_mma() {
    const uint32_t sb = smem_u32(dynsmem);
    const int tid = threadIdx.x;
    const int wid = tid >> 5, lane = tid & 31;
    const int wm = wid & 3, wn = wid >> 2;
    const int g = lane >> 2, t = lane & 3;
    const int row0 = blockIdx.x * BM;
    const int split = blockIdx.y;

    // preload -0.5 * row norms for this thread's 4 rows
    float bx4[4], by4[4];
    #pragma unroll
    for (int mi = 0; mi < 2; mi++)
        #pragma unroll
        for (int rh = 0; rh < 2; rh++) {
            int r = row0 + wm*32 + mi*16 + g + rh*8;
            bx4[mi*2+rh] = -0.5f * g_x2[r];
            by4[mi*2+rh] = -0.5f * g_y2[r];
        }

    float lm[3][4], ls[3][4];
    #pragma unroll
    for (int tt = 0; tt < 3; tt++)
        #pragma unroll
        for (int r = 0; r < 4; r++) { lm[tt][r] = -1e30f; ls[tt][r] = 0.f; }

    const __nv_bfloat16* Asm[2] = {
        (const __nv_bfloat16*)(dynsmem + SMEM_A(0)),
        (const __nv_bfloat16*)(dynsmem + SMEM_A(1)) };
    const __nv_bfloat16* Bsm[2] = {
        (const __nv_bfloat16*)(dynsmem + SMEM_B(0)),
        (const __nv_bfloat16*)(dynsmem + SMEM_B(1)) };

    for (int t0 = 0; t0 < NTILE; t0++) {
        const int c0 = split * (SN / NSPLIT) + t0 * BN;

        float dx[2][4][4], dy[2][4][4];
        #pragma unroll
        for (int mi = 0; mi < 2; mi++)
            #pragma unroll
            for (int ni = 0; ni < 4; ni++)
                #pragma unroll
                for (int k = 0; k < 4; k++) { dx[mi][ni][k] = 0.f; dy[mi][ni][k] = 0.f; }

        issue_chunk(sb, 0, 0, row0, c0, tid);
        for (int c = 0; c < NCH; c++) {
            if (c + 1 < NCH) {
                issue_chunk(sb, (c + 1) & 1, c + 1, row0, c0, tid);
                cp_wait1();
            } else {
                cp_wait0();
            }
            __syncthreads();
            int b = c & 1;
            if (c < NXCH) mma_chunk(Asm[b], Bsm[b], wm, wn, g, t, dx);
            else          mma_chunk(Asm[b], Bsm[b], wm, wn, g, t, dy);
            __syncthreads();
        }

        // ---- epilogue: fold D_x, D_y into online LSEs ----
        float cxa[4][2], cya[4][2];
        #pragma unroll
        for (int ni = 0; ni < 4; ni++) {
            int col = c0 + wn*32 + ni*8 + 2*t;
            float2 vx = *(const float2*)&g_xs2[col];
            float2 vy = *(const float2*)&g_ys2[col];
            cxa[ni][0] = -0.5f * vx.x; cxa[ni][1] = -0.5f * vx.y;
            cya[ni][0] = -0.5f * vy.x; cya[ni][1] = -0.5f * vy.y;
        }
        #pragma unroll
        for (int mi = 0; mi < 2; mi++)
            #pragma unroll
            for (int ni = 0; ni < 4; ni++)
                #pragma unroll
                for (int rh = 0; rh < 2; rh++)
                    #pragma unroll
                    for (int cc = 0; cc < 2; cc++) {
                        float ex = dx[mi][ni][rh*2+cc] + bx4[mi*2+rh] + cxa[ni][cc];
                        float ey = dy[mi][ni][rh*2+cc] + by4[mi*2+rh] + cya[ni][cc];
                        float ez = ex + ey;
                        int rr = mi*2 + rh;
                        upd(lm[0][rr], ls[0][rr], ex);
                        upd(lm[1][rr], ls[1][rr], ey);
                        upd(lm[2][rr], ls[2][rr], ez);
                    }
    }

    // ---- merge across the 4 't' lanes sharing each row ----
    #pragma unroll
    for (int tt = 0; tt < 3; tt++)
        #pragma unroll
        for (int r = 0; r < 4; r++) {
            float m = lm[tt][r], s = ls[tt][r];
            #pragma unroll
            for (int off = 1; off <= 2; off <<= 1) {
                float mo = __shfl_xor_sync(0xffffffffu, m, off);
                float so = __shfl_xor_sync(0xffffffffu, s, off);
                float M = fmaxf(m, mo);
                s = s * __expf(m - M) + so * __expf(mo - M);
                m = M;
            }
            lm[tt][r] = m; ls[tt][r] = s;
        }

    __syncthreads();
    float* red = (float*)dynsmem;   // [3][128][2][2] = 12 KB, aliases stage bufs
    if (t == 0) {
        #pragma unroll
        for (int tt = 0; tt < 3; tt++)
            #pragma unroll
            for (int mi = 0; mi < 2; mi++)
                #pragma unroll
                for (int rh = 0; rh < 2; rh++) {
                    int rl = wm*32 + mi*16 + g + rh*8;
                    red[((tt*BM + rl)*2 + wn)*2 + 0] = lm[tt][mi*2+rh];
                    red[((tt*BM + rl)*2 + wn)*2 + 1] = ls[tt][mi*2+rh];
                }
    }
    __syncthreads();
    for (int task = tid; task < 3*BM; task += NTHREADS) {
        int tt = task >> 7, rl = task & 127;
        float m0 = red[((tt*BM + rl)*2 + 0)*2 + 0], s0 = red[((tt*BM + rl)*2 + 0)*2 + 1];
        float m1 = red[((tt*BM + rl)*2 + 1)*2 + 0], s1 = red[((tt*BM + rl)*2 + 1)*2 + 1];
        float M = fmaxf(m0, m1);
        float S = s0 * __expf(m0 - M) + s1 * __expf(m1 - M);
        int gidx = (tt*BQ + row0 + rl) * NSPLIT + split;
        g_pm[gidx] = M;
        g_ps[gidx] = S;
    }
}

// ---------------- finalize: merge splits, compute mean ----------------
__global__ void finalize_kernel(float* __restrict__ out) {
    __shared__ float acc[256];
    float local = 0.f;
    for (int r = threadIdx.x; r < BQ; r += 256) {
        float lse[3];
        #pragma unroll
        for (int tt = 0; tt < 3; tt++) {
            int base = (tt*BQ + r) * NSPLIT;
            float M = -1e30f;
            #pragma unroll
            for (int s = 0; s < NSPLIT; s++) M = fmaxf(M, g_pm[base + s]);
            float S = 0.f;
            #pragma unroll
            for (int s = 0; s < NSPLIT; s++) S += g_ps[base + s] * __expf(g_pm[base + s] - M);
            lse[tt] = M + logf(S);
        }
        local += lse[2] - lse[0] - lse[1];
    }
    acc[threadIdx.x] = local;
    __syncthreads();
    #pragma unroll
    for (int o = 128; o; o >>= 1) {
        if (threadIdx.x < o) acc[threadIdx.x] += acc[threadIdx.x + o];
        __syncthreads();
    }
    if (threadIdx.x == 0) out[0] = acc[0] / (float)BQ;
}

extern "C" void kernel_launch(void* const* d_in, const int* in_sizes, int n_in,
                              void* d_out, int out_size) {
    (void)in_sizes; (void)n_in; (void)out_size;
    const float* x  = (const float*)d_in[0];
    const float* y  = (const float*)d_in[1];
    const float* xs = (const float*)d_in[2];
    const float* ys = (const float*)d_in[3];

    cudaFuncSetAttribute(mi_mma, cudaFuncAttributeMaxDynamicSharedMemorySize, SMEM_BYTES);

    const int total = BQ*DX + SN*DX + BQ*DY + SN*DY;
    prep_kernel<<<(total + 255) / 256, 256>>>(x, y, xs, ys);
    norms_kernel<<<(2*BQ + 2*SN) / 8, 256>>>(x, y, xs, ys);

    dim3 grid(BQ / BM, NSPLIT);
    mi_mma<<<grid, NTHREADS, SMEM_BYTES>>>();

    finalize_kernel<<<1, 256>>>((float*)d_out);
}

// round 9
// speedup vs baseline: 4.4731x; 2.0918x over previous
#include <cuda_runtime.h>
#include <cuda_bf16.h>
#include <cstdint>
#include <math.h>

#define BQ 4096
#define SN 8192
#define DX 256
#define DY 128
#define K2X (2*DX)         // 512: [hi(256) | lo(256)]
#define K2Y (2*DY)         // 256: [hi(128) | lo(128)]
#define BM 128
#define BN 128
#define BKC 64             // bf16 k per stage
#define NSPLIT 32
#define NTHREADS 256
#define NSTG 6             // 4 X stages + 2 Y stages per tile
#define NTILE ((SN/NSPLIT)/BN)  // 2
#define SROW 72            // smem row stride in bf16 (144 B)
#define SROWB 144

// smem: per stage {Ah, Al, Bh, Bl} each 128*144 = 18432 B; 2 stages
#define ST_STRIDE 73728
#define OFF_AH 0
#define OFF_AL 18432
#define OFF_BH 36864
#define OFF_BL 55296
#define SMEM_BYTES 147456

// ---------------- device scratch ----------------
__device__ __align__(16) __nv_bfloat16 g_xa[BQ*K2X];
__device__ __align__(16) __nv_bfloat16 g_xb[SN*K2X];
__device__ __align__(16) __nv_bfloat16 g_ya[BQ*K2Y];
__device__ __align__(16) __nv_bfloat16 g_yb[SN*K2Y];
__device__ float g_x2[BQ], g_y2[BQ], g_xs2[SN], g_ys2[SN];
__device__ float g_pm[3*BQ*NSPLIT], g_ps[3*BQ*NSPLIT];
__device__ float g_part[32];

// ---------------- helpers ----------------
__device__ __forceinline__ uint32_t smem_u32(const void* p) {
    uint32_t a;
    asm("{ .reg .u64 t; cvta.to.shared.u64 t, %1; cvt.u32.u64 %0, t; }" : "=r"(a) : "l"(p));
    return a;
}
__device__ __forceinline__ void cp16(uint32_t s, const void* g) {
    asm volatile("cp.async.cg.shared.global [%0], [%1], 16;" :: "r"(s), "l"(g));
}
__device__ __forceinline__ void cp_commit() { asm volatile("cp.async.commit_group;" ::: "memory"); }
__device__ __forceinline__ void cp_wait1()  { asm volatile("cp.async.wait_group 1;" ::: "memory"); }
__device__ __forceinline__ void cp_wait0()  { asm volatile("cp.async.wait_group 0;" ::: "memory"); }

// branchless online LSE update: exactly 1 MUFU exp
__device__ __forceinline__ void upd(float& m, float& s, float e) {
    float d = e - m;
    float t = __expf(-fabsf(d));
    if (d <= 0.f) { s += t; }
    else          { s = fmaf(s, t, 1.f); m = e; }
}

__device__ __forceinline__ void hmma(float* d, const uint32_t* a, const uint32_t* b) {
    asm volatile(
        "mma.sync.aligned.m16n8k16.row.col.f32.bf16.bf16.f32 "
        "{%0,%1,%2,%3}, {%4,%5,%6,%7}, {%8,%9}, {%0,%1,%2,%3};"
        : "+f"(d[0]), "+f"(d[1]), "+f"(d[2]), "+f"(d[3])
        : "r"(a[0]), "r"(a[1]), "r"(a[2]), "r"(a[3]), "r"(b[0]), "r"(b[1]));
}

// ---------------- prep: bf16 hi/lo split, [hi|lo] rows ----------------
__global__ void prep_kernel(const float* __restrict__ x, const float* __restrict__ y,
                            const float* __restrict__ xs, const float* __restrict__ ys) {
    int i = blockIdx.x * blockDim.x + threadIdx.x;
    const int N1 = BQ*DX, N2 = SN*DX, N3 = BQ*DY, N4 = SN*DY;
    float v; __nv_bfloat16 h, l;
    if (i < N1) {
        v = x[i]; h = __float2bfloat16(v); l = __float2bfloat16(v - __bfloat162float(h));
        int m = i / DX, k = i % DX;
        g_xa[m*K2X + k] = h; g_xa[m*K2X + DX + k] = l;
    } else if (i < N1 + N2) {
        int j = i - N1;
        v = xs[j]; h = __float2bfloat16(v); l = __float2bfloat16(v - __bfloat162float(h));
        int n = j / DX, k = j % DX;
        g_xb[n*K2X + k] = h; g_xb[n*K2X + DX + k] = l;
    } else if (i < N1 + N2 + N3) {
        int j = i - N1 - N2;
        v = y[j]; h = __float2bfloat16(v); l = __float2bfloat16(v - __bfloat162float(h));
        int m = j / DY, k = j % DY;
        g_ya[m*K2Y + k] = h; g_ya[m*K2Y + DY + k] = l;
    } else if (i < N1 + N2 + N3 + N4) {
        int j = i - N1 - N2 - N3;
        v = ys[j]; h = __float2bfloat16(v); l = __float2bfloat16(v - __bfloat162float(h));
        int n = j / DY, k = j % DY;
        g_yb[n*K2Y + k] = h; g_yb[n*K2Y + DY + k] = l;
    }
}

// ---------------- norms: one warp per row (exact fp32) ----------------
__global__ void norms_kernel(const float* __restrict__ x, const float* __restrict__ y,
                             const float* __restrict__ xs, const float* __restrict__ ys) {
    int warp = (blockIdx.x * blockDim.x + threadIdx.x) >> 5;
    int lane = threadIdx.x & 31;
    const float* src; int dim; float* dst; int row;
    if (warp < BQ)            { src = x;  dim = DX; dst = g_x2;  row = warp; }
    else if (warp < 2*BQ)     { src = y;  dim = DY; dst = g_y2;  row = warp - BQ; }
    else if (warp < 2*BQ+SN)  { src = xs; dim = DX; dst = g_xs2; row = warp - 2*BQ; }
    else                      { src = ys; dim = DY; dst = g_ys2; row = warp - 2*BQ - SN; }
    const float4* p = (const float4*)(src + (size_t)row * dim);
    float s = 0.f;
    for (int i = lane; i < dim/4; i += 32) {
        float4 v = p[i];
        s += v.x*v.x + v.y*v.y + v.z*v.z + v.w*v.w;
    }
    #pragma unroll
    for (int o = 16; o; o >>= 1) s += __shfl_xor_sync(0xffffffffu, s, o);
    if (lane == 0) dst[row] = s;
}

// ---------------- stage load (Ah, Al, Bh, Bl) via cp.async ----------------
__device__ __forceinline__ void issue_stage(uint32_t sb, int buf, int s,
                                            int row0, int c0, int tid) {
    const __nv_bfloat16 *asrc, *bsrc; int ldk, kc, loff;
    if (s < 4) { asrc = g_xa + (size_t)row0 * K2X; bsrc = g_xb + (size_t)c0 * K2X;
                 ldk = K2X; kc = s * BKC; loff = DX; }
    else       { asrc = g_ya + (size_t)row0 * K2Y; bsrc = g_yb + (size_t)c0 * K2Y;
                 ldk = K2Y; kc = (s - 4) * BKC; loff = DY; }
    uint32_t base = sb + buf * ST_STRIDE;
    #pragma unroll
    for (int i = 0; i < 4; i++) {
        int u = tid + i * NTHREADS;      // 0..1023
        int r = u >> 3, cv = u & 7;
        uint32_t so = r * SROWB + cv * 16;
        const __nv_bfloat16* ga = asrc + (size_t)r * ldk + kc + cv * 8;
        const __nv_bfloat16* gb = bsrc + (size_t)r * ldk + kc + cv * 8;
        cp16(base + OFF_AH + so, ga);
        cp16(base + OFF_AL + so, ga + loff);
        cp16(base + OFF_BH + so, gb);
        cp16(base + OFF_BL + so, gb + loff);
    }
    cp_commit();
}

// ---------------- warp mma over one 64-k stage: d += Ah*Bh + Ah*Bl + Al*Bh ----
__device__ __forceinline__ void mma_stage(const __nv_bfloat16* __restrict__ Ah,
                                          const __nv_bfloat16* __restrict__ Al,
                                          const __nv_bfloat16* __restrict__ Bh,
                                          const __nv_bfloat16* __restrict__ Bl,
                                          int wm, int wn, int g, int t,
                                          float (*d)[8][4]) {
    #pragma unroll
    for (int kk = 0; kk < 4; kk++) {
        int kc = kk * 16 + 2 * t;
        uint32_t ah[2][4], al[2][4], bh[8][2], bl[8][2];
        #pragma unroll
        for (int mi = 0; mi < 2; mi++) {
            int ro = (wm*32 + mi*16 + g) * SROW + kc;
            ah[mi][0] = *(const uint32_t*)(Ah + ro);
            ah[mi][1] = *(const uint32_t*)(Ah + ro + 8*SROW);
            ah[mi][2] = *(const uint32_t*)(Ah + ro + 8);
            ah[mi][3] = *(const uint32_t*)(Ah + ro + 8*SROW + 8);
            al[mi][0] = *(const uint32_t*)(Al + ro);
            al[mi][1] = *(const uint32_t*)(Al + ro + 8*SROW);
            al[mi][2] = *(const uint32_t*)(Al + ro + 8);
            al[mi][3] = *(const uint32_t*)(Al + ro + 8*SROW + 8);
        }
        #pragma unroll
        for (int ni = 0; ni < 8; ni++) {
            int ro = (wn*64 + ni*8 + g) * SROW + kc;
            bh[ni][0] = *(const uint32_t*)(Bh + ro);
            bh[ni][1] = *(const uint32_t*)(Bh + ro + 8);
            bl[ni][0] = *(const uint32_t*)(Bl + ro);
            bl[ni][1] = *(const uint32_t*)(Bl + ro + 8);
        }
        #pragma unroll
        for (int mi = 0; mi < 2; mi++)
            #pragma unroll
            for (int ni = 0; ni < 8; ni++) {
                hmma(d[mi][ni], ah[mi], bh[ni]);
                hmma(d[mi][ni], ah[mi], bl[ni]);
                hmma(d[mi][ni], al[mi], bh[ni]);
            }
    }
}

extern __shared__ char dynsmem[];

__global__ __launch_bounds__(NTHREADS, 1)
void mi_mma() {
    const uint32_t sb = smem_u32(dynsmem);
    const int tid = threadIdx.x;
    const int wid = tid >> 5, lane = tid & 31;
    const int wm = wid & 3, wn = wid >> 2;
    const int g = lane >> 2, t = lane & 3;
    const int row0 = blockIdx.x * BM;
    const int split = blockIdx.y;

    float bx4[4], by4[4];
    #pragma unroll
    for (int mi = 0; mi < 2; mi++)
        #pragma unroll
        for (int rh = 0; rh < 2; rh++) {
            int r = row0 + wm*32 + mi*16 + g + rh*8;
            bx4[mi*2+rh] = -0.5f * g_x2[r];
            by4[mi*2+rh] = -0.5f * g_y2[r];
        }

    float lm[3][4], ls[3][4];
    #pragma unroll
    for (int tt = 0; tt < 3; tt++)
        #pragma unroll
        for (int r = 0; r < 4; r++) { lm[tt][r] = -1e30f; ls[tt][r] = 0.f; }

    issue_stage(sb, 0, 0, row0, split * (SN / NSPLIT), tid);

    for (int t0 = 0; t0 < NTILE; t0++) {
        const int c0 = split * (SN / NSPLIT) + t0 * BN;

        float dx[2][8][4], dy[2][8][4];
        #pragma unroll
        for (int mi = 0; mi < 2; mi++)
            #pragma unroll
            for (int ni = 0; ni < 8; ni++)
                #pragma unroll
                for (int k = 0; k < 4; k++) { dx[mi][ni][k] = 0.f; dy[mi][ni][k] = 0.f; }

        #pragma unroll
        for (int s = 0; s < NSTG; s++) {
            if (s + 1 < NSTG) {
                issue_stage(sb, (s + 1) & 1, s + 1, row0, c0, tid);
                cp_wait1();
            } else if (t0 + 1 < NTILE) {
                issue_stage(sb, 0, 0, row0, c0 + BN, tid);
                cp_wait1();
            } else {
                cp_wait0();
            }
            __syncthreads();
            const char* st = dynsmem + (s & 1) * ST_STRIDE;
            const __nv_bfloat16* Ah = (const __nv_bfloat16*)(st + OFF_AH);
            const __nv_bfloat16* Al = (const __nv_bfloat16*)(st + OFF_AL);
            const __nv_bfloat16* Bh = (const __nv_bfloat16*)(st + OFF_BH);
            const __nv_bfloat16* Bl = (const __nv_bfloat16*)(st + OFF_BL);
            if (s < 4) mma_stage(Ah, Al, Bh, Bl, wm, wn, g, t, dx);
            else       mma_stage(Ah, Al, Bh, Bl, wm, wn, g, t, dy);
            __syncthreads();
        }

        // ---- epilogue: fold D_x, D_y into online LSEs (overlaps prefetch) ----
        float cxa[8][2], cya[8][2];
        #pragma unroll
        for (int ni = 0; ni < 8; ni++) {
            int col = c0 + wn*64 + ni*8 + 2*t;
            float2 vx = *(const float2*)&g_xs2[col];
            float2 vy = *(const float2*)&g_ys2[col];
            cxa[ni][0] = -0.5f * vx.x; cxa[ni][1] = -0.5f * vx.y;
            cya[ni][0] = -0.5f * vy.x; cya[ni][1] = -0.5f * vy.y;
        }
        #pragma unroll
        for (int mi = 0; mi < 2; mi++)
            #pragma unroll
            for (int ni = 0; ni < 8; ni++)
                #pragma unroll
                for (int rh = 0; rh < 2; rh++)
                    #pragma unroll
                    for (int cc = 0; cc < 2; cc++) {
                        float ex = dx[mi][ni][rh*2+cc] + bx4[mi*2+rh] + cxa[ni][cc];
                        float ey = dy[mi][ni][rh*2+cc] + by4[mi*2+rh] + cya[ni][cc];
                        float ez = ex + ey;
                        int rr = mi*2 + rh;
                        upd(lm[0][rr], ls[0][rr], ex);
                        upd(lm[1][rr], ls[1][rr], ey);
                        upd(lm[2][rr], ls[2][rr], ez);
                    }
    }

    // ---- merge across the 4 't' lanes sharing each row ----
    #pragma unroll
    for (int tt = 0; tt < 3; tt++)
        #pragma unroll
        for (int r = 0; r < 4; r++) {
            float m = lm[tt][r], s = ls[tt][r];
            #pragma unroll
            for (int off = 1; off <= 2; off <<= 1) {
                float mo = __shfl_xor_sync(0xffffffffu, m, off);
                float so = __shfl_xor_sync(0xffffffffu, s, off);
                float M = fmaxf(m, mo);
                s = s * __expf(m - M) + so * __expf(mo - M);
                m = M;
            }
            lm[tt][r] = m; ls[tt][r] = s;
        }

    __syncthreads();
    float* red = (float*)dynsmem;   // [3][128][2][2] = 6 KB, stage bufs are done
    if (t == 0) {
        #pragma unroll
        for (int tt = 0; tt < 3; tt++)
            #pragma unroll
            for (int mi = 0; mi < 2; mi++)
                #pragma unroll
                for (int rh = 0; rh < 2; rh++) {
                    int rl = wm*32 + mi*16 + g + rh*8;
                    red[((tt*BM + rl)*2 + wn)*2 + 0] = lm[tt][mi*2+rh];
                    red[((tt*BM + rl)*2 + wn)*2 + 1] = ls[tt][mi*2+rh];
                }
    }
    __syncthreads();
    for (int task = tid; task < 3*BM; task += NTHREADS) {
        int tt = task >> 7, rl = task & 127;
        float m0 = red[((tt*BM + rl)*2 + 0)*2 + 0], s0 = red[((tt*BM + rl)*2 + 0)*2 + 1];
        float m1 = red[((tt*BM + rl)*2 + 1)*2 + 0], s1 = red[((tt*BM + rl)*2 + 1)*2 + 1];
        float M = fmaxf(m0, m1);
        float S = s0 * __expf(m0 - M) + s1 * __expf(m1 - M);
        int gidx = (tt*BQ + row0 + rl) * NSPLIT + split;
        g_pm[gidx] = M;
        g_ps[gidx] = S;
    }
}

// ---------------- finalize stage 1: 32 blocks, one row per thread ----------------
__global__ void finalize_part() {
    __shared__ float acc[128];
    int r = blockIdx.x * 128 + threadIdx.x;
    float lse[3];
    #pragma unroll
    for (int tt = 0; tt < 3; tt++) {
        int base = (tt*BQ + r) * NSPLIT;
        const float4* pm4 = (const float4*)&g_pm[base];
        const float4* ps4 = (const float4*)&g_ps[base];
        float M = -1e30f;
        #pragma unroll
        for (int q = 0; q < NSPLIT/4; q++) {
            float4 v = pm4[q];
            M = fmaxf(M, fmaxf(fmaxf(v.x, v.y), fmaxf(v.z, v.w)));
        }
        float S = 0.f;
        #pragma unroll
        for (int q = 0; q < NSPLIT/4; q++) {
            float4 vm = pm4[q]; float4 vs = ps4[q];
            S += vs.x * __expf(vm.x - M) + vs.y * __expf(vm.y - M)
               + vs.z * __expf(vm.z - M) + vs.w * __expf(vm.w - M);
        }
        lse[tt] = M + logf(S);
    }
    acc[threadIdx.x] = lse[2] - lse[0] - lse[1];
    __syncthreads();
    #pragma unroll
    for (int o = 64; o; o >>= 1) {
        if (threadIdx.x < o) acc[threadIdx.x] += acc[threadIdx.x + o];
        __syncthreads();
    }
    if (threadIdx.x == 0) g_part[blockIdx.x] = acc[0];
}

// ---------------- finalize stage 2: one warp ----------------
__global__ void finalize2(float* __restrict__ out) {
    float v = g_part[threadIdx.x];
    #pragma unroll
    for (int o = 16; o; o >>= 1) v += __shfl_xor_sync(0xffffffffu, v, o);
    if (threadIdx.x == 0) out[0] = v / (float)BQ;
}

extern "C" void kernel_launch(void* const* d_in, const int* in_sizes, int n_in,
                              void* d_out, int out_size) {
    (void)in_sizes; (void)n_in; (void)out_size;
    const float* x  = (const float*)d_in[0];
    const float* y  = (const float*)d_in[1];
    const float* xs = (const float*)d_in[2];
    const float* ys = (const float*)d_in[3];

    cudaFuncSetAttribute(mi_mma, cudaFuncAttributeMaxDynamicSharedMemorySize, SMEM_BYTES);

    const int total = BQ*DX + SN*DX + BQ*DY + SN*DY;
    prep_kernel<<<(total + 255) / 256, 256>>>(x, y, xs, ys);
    norms_kernel<<<(2*BQ + 2*SN) / 8, 256>>>(x, y, xs, ys);

    dim3 grid(BQ / BM, NSPLIT);
    mi_mma<<<grid, NTHREADS, SMEM_BYTES>>>();

    finalize_part<<<BQ / 128, 128>>>();
    finalize2<<<1, 32>>>((float*)d_out);
}

// round 10
// speedup vs baseline: 4.6060x; 1.0297x over previous
#include <cuda_runtime.h>
#include <cuda_bf16.h>
#include <cstdint>
#include <math.h>

#define BQ 4096
#define SN 8192
#define DX 256
#define DY 128
#define K2X (2*DX)         // 512: [hi(256) | lo(256)]
#define K2Y (2*DY)         // 256: [hi(128) | lo(128)]
#define BM 128
#define BN 128
#define BKC 64             // bf16 k per stage
#define NSPLIT 32
#define NTHREADS 256
#define NSTG 6             // 4 X stages + 2 Y stages per tile
#define NTILE ((SN/NSPLIT)/BN)  // 2
#define SROW 72            // smem row stride in bf16 (144 B)
#define SROWB 144

// smem: per stage {Ah, Al, Bh, Bl} each 128*144 = 18432 B; 2 stages
#define ST_STRIDE 73728
#define OFF_AH 0
#define OFF_AL 18432
#define OFF_BH 36864
#define OFF_BL 55296
#define SMEM_BYTES 147456

// ---------------- device scratch ----------------
__device__ __align__(16) __nv_bfloat16 g_xa[BQ*K2X];
__device__ __align__(16) __nv_bfloat16 g_xb[SN*K2X];
__device__ __align__(16) __nv_bfloat16 g_ya[BQ*K2Y];
__device__ __align__(16) __nv_bfloat16 g_yb[SN*K2Y];
__device__ float g_x2[BQ], g_y2[BQ], g_xs2[SN], g_ys2[SN];
__device__ float g_pm[3*BQ*NSPLIT], g_ps[3*BQ*NSPLIT];
__device__ float g_part[32];

// ---------------- helpers ----------------
__device__ __forceinline__ uint32_t smem_u32(const void* p) {
    uint32_t a;
    asm("{ .reg .u64 t; cvta.to.shared.u64 t, %1; cvt.u32.u64 %0, t; }" : "=r"(a) : "l"(p));
    return a;
}
__device__ __forceinline__ void cp16(uint32_t s, const void* g) {
    asm volatile("cp.async.cg.shared.global [%0], [%1], 16;" :: "r"(s), "l"(g));
}
__device__ __forceinline__ void cp_commit() { asm volatile("cp.async.commit_group;" ::: "memory"); }
__device__ __forceinline__ void cp_wait1()  { asm volatile("cp.async.wait_group 1;" ::: "memory"); }
__device__ __forceinline__ void cp_wait0()  { asm volatile("cp.async.wait_group 0;" ::: "memory"); }

__device__ __forceinline__ void ldm_x4(uint32_t* r, uint32_t addr) {
    asm volatile("ldmatrix.sync.aligned.m8n8.x4.shared.b16 {%0,%1,%2,%3}, [%4];"
        : "=r"(r[0]), "=r"(r[1]), "=r"(r[2]), "=r"(r[3]) : "r"(addr));
}

// branchless online LSE update: exactly 1 MUFU exp
__device__ __forceinline__ void upd(float& m, float& s, float e) {
    float d = e - m;
    float t = __expf(-fabsf(d));
    if (d <= 0.f) { s += t; }
    else          { s = fmaf(s, t, 1.f); m = e; }
}

__device__ __forceinline__ void hmma(float* d, const uint32_t* a, const uint32_t* b) {
    asm volatile(
        "mma.sync.aligned.m16n8k16.row.col.f32.bf16.bf16.f32 "
        "{%0,%1,%2,%3}, {%4,%5,%6,%7}, {%8,%9}, {%0,%1,%2,%3};"
        : "+f"(d[0]), "+f"(d[1]), "+f"(d[2]), "+f"(d[3])
        : "r"(a[0]), "r"(a[1]), "r"(a[2]), "r"(a[3]), "r"(b[0]), "r"(b[1]));
}

// ---------------- prep: bf16 hi/lo split, [hi|lo] rows ----------------
__global__ void prep_kernel(const float* __restrict__ x, const float* __restrict__ y,
                            const float* __restrict__ xs, const float* __restrict__ ys) {
    int i = blockIdx.x * blockDim.x + threadIdx.x;
    const int N1 = BQ*DX, N2 = SN*DX, N3 = BQ*DY, N4 = SN*DY;
    float v; __nv_bfloat16 h, l;
    if (i < N1) {
        v = x[i]; h = __float2bfloat16(v); l = __float2bfloat16(v - __bfloat162float(h));
        int m = i / DX, k = i % DX;
        g_xa[m*K2X + k] = h; g_xa[m*K2X + DX + k] = l;
    } else if (i < N1 + N2) {
        int j = i - N1;
        v = xs[j]; h = __float2bfloat16(v); l = __float2bfloat16(v - __bfloat162float(h));
        int n = j / DX, k = j % DX;
        g_xb[n*K2X + k] = h; g_xb[n*K2X + DX + k] = l;
    } else if (i < N1 + N2 + N3) {
        int j = i - N1 - N2;
        v = y[j]; h = __float2bfloat16(v); l = __float2bfloat16(v - __bfloat162float(h));
        int m = j / DY, k = j % DY;
        g_ya[m*K2Y + k] = h; g_ya[m*K2Y + DY + k] = l;
    } else if (i < N1 + N2 + N3 + N4) {
        int j = i - N1 - N2 - N3;
        v = ys[j]; h = __float2bfloat16(v); l = __float2bfloat16(v - __bfloat162float(h));
        int n = j / DY, k = j % DY;
        g_yb[n*K2Y + k] = h; g_yb[n*K2Y + DY + k] = l;
    }
}

// ---------------- norms: one warp per row (exact fp32) ----------------
__global__ void norms_kernel(const float* __restrict__ x, const float* __restrict__ y,
                             const float* __restrict__ xs, const float* __restrict__ ys) {
    int warp = (blockIdx.x * blockDim.x + threadIdx.x) >> 5;
    int lane = threadIdx.x & 31;
    const float* src; int dim; float* dst; int row;
    if (warp < BQ)            { src = x;  dim = DX; dst = g_x2;  row = warp; }
    else if (warp < 2*BQ)     { src = y;  dim = DY; dst = g_y2;  row = warp - BQ; }
    else if (warp < 2*BQ+SN)  { src = xs; dim = DX; dst = g_xs2; row = warp - 2*BQ; }
    else                      { src = ys; dim = DY; dst = g_ys2; row = warp - 2*BQ - SN; }
    const float4* p = (const float4*)(src + (size_t)row * dim);
    float s = 0.f;
    for (int i = lane; i < dim/4; i += 32) {
        float4 v = p[i];
        s += v.x*v.x + v.y*v.y + v.z*v.z + v.w*v.w;
    }
    #pragma unroll
    for (int o = 16; o; o >>= 1) s += __shfl_xor_sync(0xffffffffu, s, o);
    if (lane == 0) dst[row] = s;
}

// ---------------- stage load (Ah, Al, Bh, Bl) via cp.async ----------------
__device__ __forceinline__ void issue_stage(uint32_t sb, int buf, int s,
                                            int row0, int c0, int tid) {
    const __nv_bfloat16 *asrc, *bsrc; int ldk, kc, loff;
    if (s < 4) { asrc = g_xa + (size_t)row0 * K2X; bsrc = g_xb + (size_t)c0 * K2X;
                 ldk = K2X; kc = s * BKC; loff = DX; }
    else       { asrc = g_ya + (size_t)row0 * K2Y; bsrc = g_yb + (size_t)c0 * K2Y;
                 ldk = K2Y; kc = (s - 4) * BKC; loff = DY; }
    uint32_t base = sb + buf * ST_STRIDE;
    #pragma unroll
    for (int i = 0; i < 4; i++) {
        int u = tid + i * NTHREADS;      // 0..1023
        int r = u >> 3, cv = u & 7;
        uint32_t so = r * SROWB + cv * 16;
        const __nv_bfloat16* ga = asrc + (size_t)r * ldk + kc + cv * 8;
        const __nv_bfloat16* gb = bsrc + (size_t)r * ldk + kc + cv * 8;
        cp16(base + OFF_AH + so, ga);
        cp16(base + OFF_AL + so, ga + loff);
        cp16(base + OFF_BH + so, gb);
        cp16(base + OFF_BL + so, gb + loff);
    }
    cp_commit();
}

// ---------------- warp mma over one 64-k stage via ldmatrix ----------------
// a_off: lane base for A 16x16 frag loads; b_off: lane base for B 16x16 pair loads.
__device__ __forceinline__ void mma_stage(uint32_t st, uint32_t a_off, uint32_t b_off,
                                          float (*d)[8][4]) {
    #pragma unroll
    for (int kk = 0; kk < 4; kk++) {
        const uint32_t kadd = kk * 32;    // 16 bf16 = 32 bytes
        uint32_t ah[2][4], al[2][4], bh[8][2], bl[8][2];
        #pragma unroll
        for (int mi = 0; mi < 2; mi++) {
            ldm_x4(ah[mi], st + OFF_AH + a_off + mi * 16 * SROWB + kadd);
            ldm_x4(al[mi], st + OFF_AL + a_off + mi * 16 * SROWB + kadd);
        }
        #pragma unroll
        for (int n2 = 0; n2 < 4; n2++) {
            ldm_x4(&bh[n2*2][0], st + OFF_BH + b_off + n2 * 16 * SROWB + kadd);
            ldm_x4(&bl[n2*2][0], st + OFF_BL + b_off + n2 * 16 * SROWB + kadd);
        }
        #pragma unroll
        for (int mi = 0; mi < 2; mi++)
            #pragma unroll
            for (int ni = 0; ni < 8; ni++) {
                hmma(d[mi][ni], ah[mi], bh[ni]);
                hmma(d[mi][ni], ah[mi], bl[ni]);
                hmma(d[mi][ni], al[mi], bh[ni]);
            }
    }
}

extern __shared__ char dynsmem[];

__global__ __launch_bounds__(NTHREADS, 1)
void mi_mma() {
    const uint32_t sb = smem_u32(dynsmem);
    const int tid = threadIdx.x;
    const int wid = tid >> 5, lane = tid & 31;
    const int wm = wid & 3, wn = wid >> 2;
    const int g = lane >> 2, t = lane & 3;
    const int row0 = blockIdx.x * BM;
    const int split = blockIdx.y;

    // ldmatrix lane address bases (byte offsets within a stage operand)
    const int rl = lane & 7, q1 = (lane >> 3) & 1, q2 = (lane >> 4) & 1;
    // A frag: mat order (row0,col0),(row8,col0),(row0,col8),(row8,col8)
    const uint32_t a_off = ((uint32_t)(wm*32 + rl + q1*8) * SROW + (uint32_t)(q2*8)) * 2;
    // B frag: mat order (row0,col0),(row0,col8),(row8,col0),(row8,col8)
    const uint32_t b_off = ((uint32_t)(wn*64 + rl + q2*8) * SROW + (uint32_t)(q1*8)) * 2;

    float bx4[4], by4[4];
    #pragma unroll
    for (int mi = 0; mi < 2; mi++)
        #pragma unroll
        for (int rh = 0; rh < 2; rh++) {
            int r = row0 + wm*32 + mi*16 + g + rh*8;
            bx4[mi*2+rh] = -0.5f * g_x2[r];
            by4[mi*2+rh] = -0.5f * g_y2[r];
        }

    float lm[3][4], ls[3][4];
    #pragma unroll
    for (int tt = 0; tt < 3; tt++)
        #pragma unroll
        for (int r = 0; r < 4; r++) { lm[tt][r] = -1e30f; ls[tt][r] = 0.f; }

    issue_stage(sb, 0, 0, row0, split * (SN / NSPLIT), tid);

    for (int t0 = 0; t0 < NTILE; t0++) {
        const int c0 = split * (SN / NSPLIT) + t0 * BN;

        float dx[2][8][4], dy[2][8][4];
        #pragma unroll
        for (int mi = 0; mi < 2; mi++)
            #pragma unroll
            for (int ni = 0; ni < 8; ni++)
                #pragma unroll
                for (int k = 0; k < 4; k++) { dx[mi][ni][k] = 0.f; dy[mi][ni][k] = 0.f; }

        #pragma unroll
        for (int s = 0; s < NSTG; s++) {
            if (s + 1 < NSTG) {
                issue_stage(sb, (s + 1) & 1, s + 1, row0, c0, tid);
                cp_wait1();
            } else if (t0 + 1 < NTILE) {
                issue_stage(sb, 0, 0, row0, c0 + BN, tid);
                cp_wait1();
            } else {
                cp_wait0();
            }
            __syncthreads();
            uint32_t st = sb + (s & 1) * ST_STRIDE;
            if (s < 4) mma_stage(st, a_off, b_off, dx);
            else       mma_stage(st, a_off, b_off, dy);
            __syncthreads();
        }

        // ---- epilogue: fold D_x, D_y into online LSEs (overlaps prefetch) ----
        float cxa[8][2], cya[8][2];
        #pragma unroll
        for (int ni = 0; ni < 8; ni++) {
            int col = c0 + wn*64 + ni*8 + 2*t;
            float2 vx = *(const float2*)&g_xs2[col];
            float2 vy = *(const float2*)&g_ys2[col];
            cxa[ni][0] = -0.5f * vx.x; cxa[ni][1] = -0.5f * vx.y;
            cya[ni][0] = -0.5f * vy.x; cya[ni][1] = -0.5f * vy.y;
        }
        #pragma unroll
        for (int mi = 0; mi < 2; mi++)
            #pragma unroll
            for (int ni = 0; ni < 8; ni++)
                #pragma unroll
                for (int rh = 0; rh < 2; rh++)
                    #pragma unroll
                    for (int cc = 0; cc < 2; cc++) {
                        float ex = dx[mi][ni][rh*2+cc] + bx4[mi*2+rh] + cxa[ni][cc];
                        float ey = dy[mi][ni][rh*2+cc] + by4[mi*2+rh] + cya[ni][cc];
                        float ez = ex + ey;
                        int rr = mi*2 + rh;
                        upd(lm[0][rr], ls[0][rr], ex);
                        upd(lm[1][rr], ls[1][rr], ey);
                        upd(lm[2][rr], ls[2][rr], ez);
                    }
    }

    // ---- merge across the 4 't' lanes sharing each row ----
    #pragma unroll
    for (int tt = 0; tt < 3; tt++)
        #pragma unroll
        for (int r = 0; r < 4; r++) {
            float m = lm[tt][r], s = ls[tt][r];
            #pragma unroll
            for (int off = 1; off <= 2; off <<= 1) {
                float mo = __shfl_xor_sync(0xffffffffu, m, off);
                float so = __shfl_xor_sync(0xffffffffu, s, off);
                float M = fmaxf(m, mo);
                s = s * __expf(m - M) + so * __expf(mo - M);
                m = M;
            }
            lm[tt][r] = m; ls[tt][r] = s;
        }

    __syncthreads();
    float* red = (float*)dynsmem;   // [3][128][2][2] = 6 KB, stage bufs are done
    if (t == 0) {
        #pragma unroll
        for (int tt = 0; tt < 3; tt++)
            #pragma unroll
            for (int mi = 0; mi < 2; mi++)
                #pragma unroll
                for (int rh = 0; rh < 2; rh++) {
                    int rr = wm*32 + mi*16 + g + rh*8;
                    red[((tt*BM + rr)*2 + wn)*2 + 0] = lm[tt][mi*2+rh];
                    red[((tt*BM + rr)*2 + wn)*2 + 1] = ls[tt][mi*2+rh];
                }
    }
    __syncthreads();
    for (int task = tid; task < 3*BM; task += NTHREADS) {
        int tt = task >> 7, rr = task & 127;
        float m0 = red[((tt*BM + rr)*2 + 0)*2 + 0], s0 = red[((tt*BM + rr)*2 + 0)*2 + 1];
        float m1 = red[((tt*BM + rr)*2 + 1)*2 + 0], s1 = red[((tt*BM + rr)*2 + 1)*2 + 1];
        float M = fmaxf(m0, m1);
        float S = s0 * __expf(m0 - M) + s1 * __expf(m1 - M);
        int gidx = (tt*BQ + row0 + rr) * NSPLIT + split;
        g_pm[gidx] = M;
        g_ps[gidx] = S;
    }
}

// ---------------- finalize stage 1: 32 blocks, one row per thread ----------------
__global__ void finalize_part() {
    __shared__ float acc[128];
    int r = blockIdx.x * 128 + threadIdx.x;
    float lse[3];
    #pragma unroll
    for (int tt = 0; tt < 3; tt++) {
        int base = (tt*BQ + r) * NSPLIT;
        const float4* pm4 = (const float4*)&g_pm[base];
        const float4* ps4 = (const float4*)&g_ps[base];
        float M = -1e30f;
        #pragma unroll
        for (int q = 0; q < NSPLIT/4; q++) {
            float4 v = pm4[q];
            M = fmaxf(M, fmaxf(fmaxf(v.x, v.y), fmaxf(v.z, v.w)));
        }
        float S = 0.f;
        #pragma unroll
        for (int q = 0; q < NSPLIT/4; q++) {
            float4 vm = pm4[q]; float4 vs = ps4[q];
            S += vs.x * __expf(vm.x - M) + vs.y * __expf(vm.y - M)
               + vs.z * __expf(vm.z - M) + vs.w * __expf(vm.w - M);
        }
        lse[tt] = M + logf(S);
    }
    acc[threadIdx.x] = lse[2] - lse[0] - lse[1];
    __syncthreads();
    #pragma unroll
    for (int o = 64; o; o >>= 1) {
        if (threadIdx.x < o) acc[threadIdx.x] += acc[threadIdx.x + o];
        __syncthreads();
    }
    if (threadIdx.x == 0) g_part[blockIdx.x] = acc[0];
}

// ---------------- finalize stage 2: one warp ----------------
__global__ void finalize2(float* __restrict__ out) {
    float v = g_part[threadIdx.x];
    #pragma unroll
    for (int o = 16; o; o >>= 1) v += __shfl_xor_sync(0xffffffffu, v, o);
    if (threadIdx.x == 0) out[0] = v / (float)BQ;
}

extern "C" void kernel_launch(void* const* d_in, const int* in_sizes, int n_in,
                              void* d_out, int out_size) {
    (void)in_sizes; (void)n_in; (void)out_size;
    const float* x  = (const float*)d_in[0];
    const float* y  = (const float*)d_in[1];
    const float* xs = (const float*)d_in[2];
    const float* ys = (const float*)d_in[3];

    cudaFuncSetAttribute(mi_mma, cudaFuncAttributeMaxDynamicSharedMemorySize, SMEM_BYTES);

    const int total = BQ*DX + SN*DX + BQ*DY + SN*DY;
    prep_kernel<<<(total + 255) / 256, 256>>>(x, y, xs, ys);
    norms_kernel<<<(2*BQ + 2*SN) / 8, 256>>>(x, y, xs, ys);

    dim3 grid(BQ / BM, NSPLIT);
    mi_mma<<<grid, NTHREADS, SMEM_BYTES>>>();

    finalize_part<<<BQ / 128, 128>>>();
    finalize2<<<1, 32>>>((float*)d_out);
}

// round 11
// speedup vs baseline: 8.2108x; 1.7826x over previous
#include <cuda_runtime.h>
#include <cuda_fp16.h>
#include <cstdint>
#include <math.h>

#define BQ 4096
#define SN 8192
#define DX 256
#define DY 128
#define BM 128
#define BN 128
#define BKC 64             // fp16 k per stage
#define NSPLIT 32
#define NTHREADS 256
#define NSTG 6             // 4 X stages + 2 Y stages per tile
#define NTILE ((SN/NSPLIT)/BN)  // 2
#define SROW 72            // smem row stride in fp16 (144 B)
#define SROWB 144

// smem: per stage {A, B} each 128*144 = 18432 B; 2 stages
#define ST_STRIDE 36864
#define OFF_A 0
#define OFF_B 18432
#define SMEM_BYTES 73728

// ---------------- device scratch ----------------
__device__ __align__(16) __half g_xa[BQ*DX];
__device__ __align__(16) __half g_xb[SN*DX];
__device__ __align__(16) __half g_ya[BQ*DY];
__device__ __align__(16) __half g_yb[SN*DY];
__device__ float g_x2[BQ], g_y2[BQ], g_xs2[SN], g_ys2[SN];
__device__ float g_pm[3*BQ*NSPLIT], g_ps[3*BQ*NSPLIT];
__device__ float g_part[32];

// ---------------- helpers ----------------
__device__ __forceinline__ uint32_t smem_u32(const void* p) {
    uint32_t a;
    asm("{ .reg .u64 t; cvta.to.shared.u64 t, %1; cvt.u32.u64 %0, t; }" : "=r"(a) : "l"(p));
    return a;
}
__device__ __forceinline__ void cp16(uint32_t s, const void* g) {
    asm volatile("cp.async.cg.shared.global [%0], [%1], 16;" :: "r"(s), "l"(g));
}
__device__ __forceinline__ void cp_commit() { asm volatile("cp.async.commit_group;" ::: "memory"); }
__device__ __forceinline__ void cp_wait1()  { asm volatile("cp.async.wait_group 1;" ::: "memory"); }
__device__ __forceinline__ void cp_wait0()  { asm volatile("cp.async.wait_group 0;" ::: "memory"); }

__device__ __forceinline__ void ldm_x4(uint32_t* r, uint32_t addr) {
    asm volatile("ldmatrix.sync.aligned.m8n8.x4.shared.b16 {%0,%1,%2,%3}, [%4];"
        : "=r"(r[0]), "=r"(r[1]), "=r"(r[2]), "=r"(r[3]) : "r"(addr));
}

// branchless online LSE update: exactly 1 MUFU exp
__device__ __forceinline__ void upd(float& m, float& s, float e) {
    float d = e - m;
    float t = __expf(-fabsf(d));
    if (d <= 0.f) { s += t; }
    else          { s = fmaf(s, t, 1.f); m = e; }
}

__device__ __forceinline__ void hmma(float* d, const uint32_t* a, const uint32_t* b) {
    asm volatile(
        "mma.sync.aligned.m16n8k16.row.col.f32.f16.f16.f32 "
        "{%0,%1,%2,%3}, {%4,%5,%6,%7}, {%8,%9}, {%0,%1,%2,%3};"
        : "+f"(d[0]), "+f"(d[1]), "+f"(d[2]), "+f"(d[3])
        : "r"(a[0]), "r"(a[1]), "r"(a[2]), "r"(a[3]), "r"(b[0]), "r"(b[1]));
}

// ---------------- prep: fp16 convert ----------------
__global__ void prep_kernel(const float* __restrict__ x, const float* __restrict__ y,
                            const float* __restrict__ xs, const float* __restrict__ ys) {
    int i4 = blockIdx.x * blockDim.x + threadIdx.x;   // one float4 per thread
    const int N1 = BQ*DX/4, N2 = SN*DX/4, N3 = BQ*DY/4, N4 = SN*DY/4;
    const float4* src; __half* dst; int j;
    if (i4 < N1)                { src = (const float4*)x;  dst = g_xa; j = i4; }
    else if (i4 < N1+N2)        { src = (const float4*)xs; dst = g_xb; j = i4 - N1; }
    else if (i4 < N1+N2+N3)     { src = (const float4*)y;  dst = g_ya; j = i4 - N1 - N2; }
    else if (i4 < N1+N2+N3+N4)  { src = (const float4*)ys; dst = g_yb; j = i4 - N1 - N2 - N3; }
    else return;
    float4 v = src[j];
    __half2* d2 = (__half2*)(dst + j*4);
    d2[0] = __floats2half2_rn(v.x, v.y);
    d2[1] = __floats2half2_rn(v.z, v.w);
}

// ---------------- norms: one warp per row (exact fp32) ----------------
__global__ void norms_kernel(const float* __restrict__ x, const float* __restrict__ y,
                             const float* __restrict__ xs, const float* __restrict__ ys) {
    int warp = (blockIdx.x * blockDim.x + threadIdx.x) >> 5;
    int lane = threadIdx.x & 31;
    const float* src; int dim; float* dst; int row;
    if (warp < BQ)            { src = x;  dim = DX; dst = g_x2;  row = warp; }
    else if (warp < 2*BQ)     { src = y;  dim = DY; dst = g_y2;  row = warp - BQ; }
    else if (warp < 2*BQ+SN)  { src = xs; dim = DX; dst = g_xs2; row = warp - 2*BQ; }
    else                      { src = ys; dim = DY; dst = g_ys2; row = warp - 2*BQ - SN; }
    const float4* p = (const float4*)(src + (size_t)row * dim);
    float s = 0.f;
    for (int i = lane; i < dim/4; i += 32) {
        float4 v = p[i];
        s += v.x*v.x + v.y*v.y + v.z*v.z + v.w*v.w;
    }
    #pragma unroll
    for (int o = 16; o; o >>= 1) s += __shfl_xor_sync(0xffffffffu, s, o);
    if (lane == 0) dst[row] = s;
}

// ---------------- stage load (A, B) via cp.async ----------------
__device__ __forceinline__ void issue_stage(uint32_t sb, int buf, int s,
                                            int row0, int c0, int tid) {
    const __half *asrc, *bsrc; int ldk, kc;
    if (s < 4) { asrc = g_xa + (size_t)row0 * DX; bsrc = g_xb + (size_t)c0 * DX;
                 ldk = DX; kc = s * BKC; }
    else       { asrc = g_ya + (size_t)row0 * DY; bsrc = g_yb + (size_t)c0 * DY;
                 ldk = DY; kc = (s - 4) * BKC; }
    uint32_t base = sb + buf * ST_STRIDE;
    #pragma unroll
    for (int i = 0; i < 4; i++) {
        int u = tid + i * NTHREADS;      // 0..1023
        int r = u >> 3, cv = u & 7;
        uint32_t so = r * SROWB + cv * 16;
        cp16(base + OFF_A + so, asrc + (size_t)r * ldk + kc + cv * 8);
        cp16(base + OFF_B + so, bsrc + (size_t)r * ldk + kc + cv * 8);
    }
    cp_commit();
}

// ---------------- warp mma over one 64-k stage via ldmatrix ----------------
__device__ __forceinline__ void mma_stage(uint32_t st, uint32_t a_off, uint32_t b_off,
                                          float (*d)[8][4]) {
    #pragma unroll
    for (int kk = 0; kk < 4; kk++) {
        const uint32_t kadd = kk * 32;    // 16 fp16 = 32 bytes
        uint32_t a[2][4], b[8][2];
        #pragma unroll
        for (int mi = 0; mi < 2; mi++)
            ldm_x4(a[mi], st + OFF_A + a_off + mi * 16 * SROWB + kadd);
        #pragma unroll
        for (int n2 = 0; n2 < 4; n2++)
            ldm_x4(&b[n2*2][0], st + OFF_B + b_off + n2 * 16 * SROWB + kadd);
        #pragma unroll
        for (int mi = 0; mi < 2; mi++)
            #pragma unroll
            for (int ni = 0; ni < 8; ni++)
                hmma(d[mi][ni], a[mi], b[ni]);
    }
}

extern __shared__ char dynsmem[];

__global__ __launch_bounds__(NTHREADS, 1)
void mi_mma() {
    const uint32_t sb = smem_u32(dynsmem);
    const int tid = threadIdx.x;
    const int wid = tid >> 5, lane = tid & 31;
    const int wm = wid & 3, wn = wid >> 2;
    const int g = lane >> 2, t = lane & 3;
    const int row0 = blockIdx.x * BM;
    const int split = blockIdx.y;

    // ldmatrix lane address bases (byte offsets within a stage operand)
    const int rl = lane & 7, q1 = (lane >> 3) & 1, q2 = (lane >> 4) & 1;
    const uint32_t a_off = ((uint32_t)(wm*32 + rl + q1*8) * SROW + (uint32_t)(q2*8)) * 2;
    const uint32_t b_off = ((uint32_t)(wn*64 + rl + q2*8) * SROW + (uint32_t)(q1*8)) * 2;

    float bx4[4], by4[4];
    #pragma unroll
    for (int mi = 0; mi < 2; mi++)
        #pragma unroll
        for (int rh = 0; rh < 2; rh++) {
            int r = row0 + wm*32 + mi*16 + g + rh*8;
            bx4[mi*2+rh] = -0.5f * g_x2[r];
            by4[mi*2+rh] = -0.5f * g_y2[r];
        }

    float lm[3][4], ls[3][4];
    #pragma unroll
    for (int tt = 0; tt < 3; tt++)
        #pragma unroll
        for (int r = 0; r < 4; r++) { lm[tt][r] = -1e30f; ls[tt][r] = 0.f; }

    issue_stage(sb, 0, 0, row0, split * (SN / NSPLIT), tid);

    for (int t0 = 0; t0 < NTILE; t0++) {
        const int c0 = split * (SN / NSPLIT) + t0 * BN;

        float dx[2][8][4], dy[2][8][4];
        #pragma unroll
        for (int mi = 0; mi < 2; mi++)
            #pragma unroll
            for (int ni = 0; ni < 8; ni++)
                #pragma unroll
                for (int k = 0; k < 4; k++) { dx[mi][ni][k] = 0.f; dy[mi][ni][k] = 0.f; }

        #pragma unroll
        for (int s = 0; s < NSTG; s++) {
            if (s + 1 < NSTG) {
                issue_stage(sb, (s + 1) & 1, s + 1, row0, c0, tid);
                cp_wait1();
            } else if (t0 + 1 < NTILE) {
                issue_stage(sb, 0, 0, row0, c0 + BN, tid);
                cp_wait1();
            } else {
                cp_wait0();
            }
            __syncthreads();
            uint32_t st = sb + (s & 1) * ST_STRIDE;
            if (s < 4) mma_stage(st, a_off, b_off, dx);
            else       mma_stage(st, a_off, b_off, dy);
            __syncthreads();
        }

        // ---- epilogue: fold D_x, D_y into online LSEs (overlaps prefetch) ----
        float cxa[8][2], cya[8][2];
        #pragma unroll
        for (int ni = 0; ni < 8; ni++) {
            int col = c0 + wn*64 + ni*8 + 2*t;
            float2 vx = *(const float2*)&g_xs2[col];
            float2 vy = *(const float2*)&g_ys2[col];
            cxa[ni][0] = -0.5f * vx.x; cxa[ni][1] = -0.5f * vx.y;
            cya[ni][0] = -0.5f * vy.x; cya[ni][1] = -0.5f * vy.y;
        }
        #pragma unroll
        for (int mi = 0; mi < 2; mi++)
            #pragma unroll
            for (int ni = 0; ni < 8; ni++)
                #pragma unroll
                for (int rh = 0; rh < 2; rh++)
                    #pragma unroll
                    for (int cc = 0; cc < 2; cc++) {
                        float ex = dx[mi][ni][rh*2+cc] + bx4[mi*2+rh] + cxa[ni][cc];
                        float ey = dy[mi][ni][rh*2+cc] + by4[mi*2+rh] + cya[ni][cc];
                        float ez = ex + ey;
                        int rr = mi*2 + rh;
                        upd(lm[0][rr], ls[0][rr], ex);
                        upd(lm[1][rr], ls[1][rr], ey);
                        upd(lm[2][rr], ls[2][rr], ez);
                    }
    }

    // ---- merge across the 4 't' lanes sharing each row ----
    #pragma unroll
    for (int tt = 0; tt < 3; tt++)
        #pragma unroll
        for (int r = 0; r < 4; r++) {
            float m = lm[tt][r], s = ls[tt][r];
            #pragma unroll
            for (int off = 1; off <= 2; off <<= 1) {
                float mo = __shfl_xor_sync(0xffffffffu, m, off);
                float so = __shfl_xor_sync(0xffffffffu, s, off);
                float M = fmaxf(m, mo);
                s = s * __expf(m - M) + so * __expf(mo - M);
                m = M;
            }
            lm[tt][r] = m; ls[tt][r] = s;
        }

    __syncthreads();
    float* red = (float*)dynsmem;   // [3][128][2][2] = 6 KB, stage bufs are done
    if (t == 0) {
        #pragma unroll
        for (int tt = 0; tt < 3; tt++)
            #pragma unroll
            for (int mi = 0; mi < 2; mi++)
                #pragma unroll
                for (int rh = 0; rh < 2; rh++) {
                    int rr = wm*32 + mi*16 + g + rh*8;
                    red[((tt*BM + rr)*2 + wn)*2 + 0] = lm[tt][mi*2+rh];
                    red[((tt*BM + rr)*2 + wn)*2 + 1] = ls[tt][mi*2+rh];
                }
    }
    __syncthreads();
    for (int task = tid; task < 3*BM; task += NTHREADS) {
        int tt = task >> 7, rr = task & 127;
        float m0 = red[((tt*BM + rr)*2 + 0)*2 + 0], s0 = red[((tt*BM + rr)*2 + 0)*2 + 1];
        float m1 = red[((tt*BM + rr)*2 + 1)*2 + 0], s1 = red[((tt*BM + rr)*2 + 1)*2 + 1];
        float M = fmaxf(m0, m1);
        float S = s0 * __expf(m0 - M) + s1 * __expf(m1 - M);
        int gidx = (tt*BQ + row0 + rr) * NSPLIT + split;
        g_pm[gidx] = M;
        g_ps[gidx] = S;
    }
}

// ---------------- finalize stage 1: 32 blocks, one row per thread ----------------
__global__ void finalize_part() {
    __shared__ float acc[128];
    int r = blockIdx.x * 128 + threadIdx.x;
    float lse[3];
    #pragma unroll
    for (int tt = 0; tt < 3; tt++) {
        int base = (tt*BQ + r) * NSPLIT;
        const float4* pm4 = (const float4*)&g_pm[base];
        const float4* ps4 = (const float4*)&g_ps[base];
        float M = -1e30f;
        #pragma unroll
        for (int q = 0; q < NSPLIT/4; q++) {
            float4 v = pm4[q];
            M = fmaxf(M, fmaxf(fmaxf(v.x, v.y), fmaxf(v.z, v.w)));
        }
        float S = 0.f;
        #pragma unroll
        for (int q = 0; q < NSPLIT/4; q++) {
            float4 vm = pm4[q]; float4 vs = ps4[q];
            S += vs.x * __expf(vm.x - M) + vs.y * __expf(vm.y - M)
               + vs.z * __expf(vm.z - M) + vs.w * __expf(vm.w - M);
        }
        lse[tt] = M + logf(S);
    }
    acc[threadIdx.x] = lse[2] - lse[0] - lse[1];
    __syncthreads();
    #pragma unroll
    for (int o = 64; o; o >>= 1) {
        if (threadIdx.x < o) acc[threadIdx.x] += acc[threadIdx.x + o];
        __syncthreads();
    }
    if (threadIdx.x == 0) g_part[blockIdx.x] = acc[0];
}

// ---------------- finalize stage 2: one warp ----------------
__global__ void finalize2(float* __restrict__ out) {
    float v = g_part[threadIdx.x];
    #pragma unroll
    for (int o = 16; o; o >>= 1) v += __shfl_xor_sync(0xffffffffu, v, o);
    if (threadIdx.x == 0) out[0] = v / (float)BQ;
}

extern "C" void kernel_launch(void* const* d_in, const int* in_sizes, int n_in,
                              void* d_out, int out_size) {
    (void)in_sizes; (void)n_in; (void)out_size;
    const float* x  = (const float*)d_in[0];
    const float* y  = (const float*)d_in[1];
    const float* xs = (const float*)d_in[2];
    const float* ys = (const float*)d_in[3];

    cudaFuncSetAttribute(mi_mma, cudaFuncAttributeMaxDynamicSharedMemorySize, SMEM_BYTES);

    const int total4 = (BQ*DX + SN*DX + BQ*DY + SN*DY) / 4;
    prep_kernel<<<(total4 + 255) / 256, 256>>>(x, y, xs, ys);
    norms_kernel<<<(2*BQ + 2*SN) / 8, 256>>>(x, y, xs, ys);

    dim3 grid(BQ / BM, NSPLIT);
    mi_mma<<<grid, NTHREADS, SMEM_BYTES>>>();

    finalize_part<<<BQ / 128, 128>>>();
    finalize2<<<1, 32>>>((float*)d_out);
}

// round 12
// speedup vs baseline: 8.7165x; 1.0616x over previous
#include <cuda_runtime.h>
#include <cuda_fp16.h>
#include <cstdint>
#include <math.h>

#define BQ 4096
#define SN 8192
#define DX 256
#define DY 128
#define BM 128
#define BN 128
#define BKC 64             // fp16 k per stage
#define NSPLIT 32
#define NTHREADS 256
#define NSTG 6             // 4 X stages + 2 Y stages per tile
#define NTILE ((SN/NSPLIT)/BN)  // 2
#define NSS (NTILE*NSTG)   // 12 global stages per CTA
#define SROW 72            // smem row stride in fp16 (144 B)
#define SROWB 144

// smem: per stage {A, B} each 128*144 = 18432 B; 3 circular stages
#define ST_STRIDE 36864
#define OFF_A 0
#define OFF_B 18432
#define SMEM_BYTES (3*ST_STRIDE)   // 110592

// ---------------- device scratch ----------------
__device__ __align__(16) __half g_xa[BQ*DX];
__device__ __align__(16) __half g_xb[SN*DX];
__device__ __align__(16) __half g_ya[BQ*DY];
__device__ __align__(16) __half g_yb[SN*DY];
__device__ float g_x2[BQ], g_y2[BQ], g_xs2[SN], g_ys2[SN];
__device__ float g_pm[3*BQ*NSPLIT], g_ps[3*BQ*NSPLIT];
__device__ float g_part[96];

// ---------------- helpers ----------------
__device__ __forceinline__ uint32_t smem_u32(const void* p) {
    uint32_t a;
    asm("{ .reg .u64 t; cvta.to.shared.u64 t, %1; cvt.u32.u64 %0, t; }" : "=r"(a) : "l"(p));
    return a;
}
__device__ __forceinline__ void cp16(uint32_t s, const void* g) {
    asm volatile("cp.async.cg.shared.global [%0], [%1], 16;" :: "r"(s), "l"(g));
}
__device__ __forceinline__ void cp_commit() { asm volatile("cp.async.commit_group;" ::: "memory"); }
__device__ __forceinline__ void cp_wait1()  { asm volatile("cp.async.wait_group 1;" ::: "memory"); }
__device__ __forceinline__ void cp_wait0()  { asm volatile("cp.async.wait_group 0;" ::: "memory"); }

__device__ __forceinline__ void ldm_x4(uint32_t* r, uint32_t addr) {
    asm volatile("ldmatrix.sync.aligned.m8n8.x4.shared.b16 {%0,%1,%2,%3}, [%4];"
        : "=r"(r[0]), "=r"(r[1]), "=r"(r[2]), "=r"(r[3]) : "r"(addr));
}

__device__ __forceinline__ void hmma(float* d, const uint32_t* a, const uint32_t* b) {
    asm volatile(
        "mma.sync.aligned.m16n8k16.row.col.f32.f16.f16.f32 "
        "{%0,%1,%2,%3}, {%4,%5,%6,%7}, {%8,%9}, {%0,%1,%2,%3};"
        : "+f"(d[0]), "+f"(d[1]), "+f"(d[2]), "+f"(d[3])
        : "r"(a[0]), "r"(a[1]), "r"(a[2]), "r"(a[3]), "r"(b[0]), "r"(b[1]));
}

// ---------------- fused prep (fp16 convert) + norms: one warp per row ----------------
__global__ void prep_norms(const float* __restrict__ x, const float* __restrict__ y,
                           const float* __restrict__ xs, const float* __restrict__ ys) {
    int warp = (blockIdx.x * blockDim.x + threadIdx.x) >> 5;
    int lane = threadIdx.x & 31;
    const float* src; int dim; float* ndst; __half* hdst; int row;
    if (warp < BQ)            { src = x;  dim = DX; ndst = g_x2;  hdst = g_xa; row = warp; }
    else if (warp < 2*BQ)     { src = y;  dim = DY; ndst = g_y2;  hdst = g_ya; row = warp - BQ; }
    else if (warp < 2*BQ+SN)  { src = xs; dim = DX; ndst = g_xs2; hdst = g_xb; row = warp - 2*BQ; }
    else                      { src = ys; dim = DY; ndst = g_ys2; hdst = g_yb; row = warp - 2*BQ - SN; }
    const float4* p = (const float4*)(src + (size_t)row * dim);
    uint2* hp = (uint2*)(hdst + (size_t)row * dim);
    float s = 0.f;
    for (int i = lane; i < dim/4; i += 32) {
        float4 v = p[i];
        s += v.x*v.x + v.y*v.y + v.z*v.z + v.w*v.w;
        __half2 h0 = __floats2half2_rn(v.x, v.y);
        __half2 h1 = __floats2half2_rn(v.z, v.w);
        hp[i] = make_uint2(*(const uint32_t*)&h0, *(const uint32_t*)&h1);
    }
    #pragma unroll
    for (int o = 16; o; o >>= 1) s += __shfl_xor_sync(0xffffffffu, s, o);
    if (lane == 0) ndst[row] = s;
}

// ---------------- stage load (A, B) via cp.async; buf = ss % 3 ----------------
__device__ __forceinline__ void issue_stage(uint32_t sb, int ss, int row0,
                                            int sc0, int tid) {
    const int tile = ss / NSTG, s = ss % NSTG;
    const int c0 = sc0 + tile * BN;
    const __half *asrc, *bsrc; int ldk, kc;
    if (s < 4) { asrc = g_xa + (size_t)row0 * DX; bsrc = g_xb + (size_t)c0 * DX;
                 ldk = DX; kc = s * BKC; }
    else       { asrc = g_ya + (size_t)row0 * DY; bsrc = g_yb + (size_t)c0 * DY;
                 ldk = DY; kc = (s - 4) * BKC; }
    uint32_t base = sb + (ss % 3) * ST_STRIDE;
    #pragma unroll
    for (int i = 0; i < 4; i++) {
        int u = tid + i * NTHREADS;      // 0..1023
        int r = u >> 3, cv = u & 7;
        uint32_t so = r * SROWB + cv * 16;
        cp16(base + OFF_A + so, asrc + (size_t)r * ldk + kc + cv * 8);
        cp16(base + OFF_B + so, bsrc + (size_t)r * ldk + kc + cv * 8);
    }
    cp_commit();
}

// ---------------- warp mma over one 64-k stage via ldmatrix ----------------
__device__ __forceinline__ void mma_stage(uint32_t st, uint32_t a_off, uint32_t b_off,
                                          float (*d)[8][4]) {
    #pragma unroll
    for (int kk = 0; kk < 4; kk++) {
        const uint32_t kadd = kk * 32;    // 16 fp16 = 32 bytes
        uint32_t a[2][4], b[8][2];
        #pragma unroll
        for (int mi = 0; mi < 2; mi++)
            ldm_x4(a[mi], st + OFF_A + a_off + mi * 16 * SROWB + kadd);
        #pragma unroll
        for (int n2 = 0; n2 < 4; n2++)
            ldm_x4(&b[n2*2][0], st + OFF_B + b_off + n2 * 16 * SROWB + kadd);
        #pragma unroll
        for (int mi = 0; mi < 2; mi++)
            #pragma unroll
            for (int ni = 0; ni < 8; ni++)
                hmma(d[mi][ni], a[mi], b[ni]);
    }
}

extern __shared__ char dynsmem[];

__global__ __launch_bounds__(NTHREADS, 1)
void mi_mma() {
    const uint32_t sb = smem_u32(dynsmem);
    const int tid = threadIdx.x;
    const int wid = tid >> 5, lane = tid & 31;
    const int wm = wid & 3, wn = wid >> 2;
    const int g = lane >> 2, t = lane & 3;
    const int row0 = blockIdx.x * BM;
    const int split = blockIdx.y;
    const int sc0 = split * (SN / NSPLIT);

    // ldmatrix lane address bases (byte offsets within a stage operand)
    const int rl = lane & 7, q1 = (lane >> 3) & 1, q2 = (lane >> 4) & 1;
    const uint32_t a_off = ((uint32_t)(wm*32 + rl + q1*8) * SROW + (uint32_t)(q2*8)) * 2;
    const uint32_t b_off = ((uint32_t)(wn*64 + rl + q2*8) * SROW + (uint32_t)(q1*8)) * 2;

    float bx4[4], by4[4];
    #pragma unroll
    for (int mi = 0; mi < 2; mi++)
        #pragma unroll
        for (int rh = 0; rh < 2; rh++) {
            int r = row0 + wm*32 + mi*16 + g + rh*8;
            bx4[mi*2+rh] = -0.5f * g_x2[r];
            by4[mi*2+rh] = -0.5f * g_y2[r];
        }

    // lm[2] is implicit: mZ = mX + mY at all times
    float lm[3][4], ls[3][4];
    #pragma unroll
    for (int tt = 0; tt < 3; tt++)
        #pragma unroll
        for (int r = 0; r < 4; r++) { lm[tt][r] = -1e30f; ls[tt][r] = 0.f; }

    issue_stage(sb, 0, row0, sc0, tid);
    issue_stage(sb, 1, row0, sc0, tid);

    for (int t0 = 0; t0 < NTILE; t0++) {
        const int c0 = sc0 + t0 * BN;

        float dx[2][8][4], dy[2][8][4];
        #pragma unroll
        for (int mi = 0; mi < 2; mi++)
            #pragma unroll
            for (int ni = 0; ni < 8; ni++)
                #pragma unroll
                for (int k = 0; k < 4; k++) { dx[mi][ni][k] = 0.f; dy[mi][ni][k] = 0.f; }

        #pragma unroll
        for (int s = 0; s < NSTG; s++) {
            const int ss = t0 * NSTG + s;
            if (ss == NSS - 1) cp_wait0(); else cp_wait1();
            __syncthreads();                      // data ready + prev readers done
            if (ss + 2 < NSS) issue_stage(sb, ss + 2, row0, sc0, tid);
            uint32_t st = sb + (ss % 3) * ST_STRIDE;
            if (s < 4) mma_stage(st, a_off, b_off, dx);
            else       mma_stage(st, a_off, b_off, dy);
        }

        // ---- epilogue: fold D_x, D_y into online LSEs (cp.async for next tile in flight) ----
        float cxa[8][2], cya[8][2];
        #pragma unroll
        for (int ni = 0; ni < 8; ni++) {
            int col = c0 + wn*64 + ni*8 + 2*t;
            float2 vx = *(const float2*)&g_xs2[col];
            float2 vy = *(const float2*)&g_ys2[col];
            cxa[ni][0] = -0.5f * vx.x; cxa[ni][1] = -0.5f * vx.y;
            cya[ni][0] = -0.5f * vy.x; cya[ni][1] = -0.5f * vy.y;
        }
        #pragma unroll
        for (int mi = 0; mi < 2; mi++)
            #pragma unroll
            for (int ni = 0; ni < 8; ni++)
                #pragma unroll
                for (int rh = 0; rh < 2; rh++)
                    #pragma unroll
                    for (int cc = 0; cc < 2; cc++) {
                        const int rr = mi*2 + rh;
                        float ex = dx[mi][ni][rh*2+cc] + bx4[rr] + cxa[ni][cc];
                        float ey = dy[mi][ni][rh*2+cc] + by4[rr] + cya[ni][cc];
                        // X update
                        float dXv = ex - lm[0][rr];
                        float tX = __expf(-fabsf(dXv));
                        bool fX = dXv > 0.f;
                        ls[0][rr] = fX ? fmaf(ls[0][rr], tX, 1.f) : ls[0][rr] + tX;
                        lm[0][rr] = fX ? ex : lm[0][rr];
                        float u  = fX ? 1.f : tX;
                        float rx = fX ? tX : 1.f;
                        // Y update
                        float dYv = ey - lm[1][rr];
                        float tY = __expf(-fabsf(dYv));
                        bool fY = dYv > 0.f;
                        ls[1][rr] = fY ? fmaf(ls[1][rr], tY, 1.f) : ls[1][rr] + tY;
                        lm[1][rr] = fY ? ey : lm[1][rr];
                        float v  = fY ? 1.f : tY;
                        float ry = fY ? tY : 1.f;
                        // Z update: shift tracks mX+mY, no exp needed
                        ls[2][rr] = fmaf(ls[2][rr], rx * ry, u * v);
                    }
    }

    // materialize mZ
    #pragma unroll
    for (int r = 0; r < 4; r++) lm[2][r] = lm[0][r] + lm[1][r];

    // ---- merge across the 4 't' lanes sharing each row ----
    #pragma unroll
    for (int tt = 0; tt < 3; tt++)
        #pragma unroll
        for (int r = 0; r < 4; r++) {
            float m = lm[tt][r], s = ls[tt][r];
            #pragma unroll
            for (int off = 1; off <= 2; off <<= 1) {
                float mo = __shfl_xor_sync(0xffffffffu, m, off);
                float so = __shfl_xor_sync(0xffffffffu, s, off);
                float M = fmaxf(m, mo);
                s = s * __expf(m - M) + so * __expf(mo - M);
                m = M;
            }
            lm[tt][r] = m; ls[tt][r] = s;
        }

    __syncthreads();
    float* red = (float*)dynsmem;   // [3][128][2][2] = 6 KB, stage bufs are done
    if (t == 0) {
        #pragma unroll
        for (int tt = 0; tt < 3; tt++)
            #pragma unroll
            for (int mi = 0; mi < 2; mi++)
                #pragma unroll
                for (int rh = 0; rh < 2; rh++) {
                    int rr = wm*32 + mi*16 + g + rh*8;
                    red[((tt*BM + rr)*2 + wn)*2 + 0] = lm[tt][mi*2+rh];
                    red[((tt*BM + rr)*2 + wn)*2 + 1] = ls[tt][mi*2+rh];
                }
    }
    __syncthreads();
    for (int task = tid; task < 3*BM; task += NTHREADS) {
        int tt = task >> 7, rr = task & 127;
        float m0 = red[((tt*BM + rr)*2 + 0)*2 + 0], s0 = red[((tt*BM + rr)*2 + 0)*2 + 1];
        float m1 = red[((tt*BM + rr)*2 + 1)*2 + 0], s1 = red[((tt*BM + rr)*2 + 1)*2 + 1];
        float M = fmaxf(m0, m1);
        float S = s0 * __expf(m0 - M) + s1 * __expf(m1 - M);
        int gidx = (tt*BQ + row0 + rr) * NSPLIT + split;
        g_pm[gidx] = M;
        g_ps[gidx] = S;
    }
}

// ---------------- finalize stage 1: 96 blocks, one (row,term) per thread ----------------
__global__ void finalize_part() {
    __shared__ float acc[128];
    int task = blockIdx.x * 128 + threadIdx.x;    // 0..12287 = tt*BQ + r
    int base = task * NSPLIT;
    const float4* pm4 = (const float4*)&g_pm[base];
    const float4* ps4 = (const float4*)&g_ps[base];
    float M = -1e30f;
    #pragma unroll
    for (int q = 0; q < NSPLIT/4; q++) {
        float4 v = pm4[q];
        M = fmaxf(M, fmaxf(fmaxf(v.x, v.y), fmaxf(v.z, v.w)));
    }
    float S = 0.f;
    #pragma unroll
    for (int q = 0; q < NSPLIT/4; q++) {
        float4 vm = pm4[q]; float4 vs = ps4[q];
        S += vs.x * __expf(vm.x - M) + vs.y * __expf(vm.y - M)
           + vs.z * __expf(vm.z - M) + vs.w * __expf(vm.w - M);
    }
    float lse = M + logf(S);
    int tt = task >> 12;                           // BQ = 4096
    acc[threadIdx.x] = (tt == 2) ? lse : -lse;
    __syncthreads();
    #pragma unroll
    for (int o = 64; o; o >>= 1) {
        if (threadIdx.x < o) acc[threadIdx.x] += acc[threadIdx.x + o];
        __syncthreads();
    }
    if (threadIdx.x == 0) g_part[blockIdx.x] = acc[0];
}

// ---------------- finalize stage 2 ----------------
__global__ void finalize2(float* __restrict__ out) {
    float v = (threadIdx.x < 96) ? g_part[threadIdx.x] : 0.f;
    #pragma unroll
    for (int o = 16; o; o >>= 1) v += __shfl_xor_sync(0xffffffffu, v, o);
    __shared__ float w[4];
    if ((threadIdx.x & 31) == 0) w[threadIdx.x >> 5] = v;
    __syncthreads();
    if (threadIdx.x == 0) out[0] = (w[0] + w[1] + w[2] + w[3]) / (float)BQ;
}

extern "C" void kernel_launch(void* const* d_in, const int* in_sizes, int n_in,
                              void* d_out, int out_size) {
    (void)in_sizes; (void)n_in; (void)out_size;
    const float* x  = (const float*)d_in[0];
    const float* y  = (const float*)d_in[1];
    const float* xs = (const float*)d_in[2];
    const float* ys = (const float*)d_in[3];

    cudaFuncSetAttribute(mi_mma, cudaFuncAttributeMaxDynamicSharedMemorySize, SMEM_BYTES);

    prep_norms<<<(2*BQ + 2*SN) / 8, 256>>>(x, y, xs, ys);

    dim3 grid(BQ / BM, NSPLIT);
    mi_mma<<<grid, NTHREADS, SMEM_BYTES>>>();

    finalize_part<<<96, 128>>>();
    finalize2<<<1, 128>>>((float*)d_out);
}

// round 17
// speedup vs baseline: 8.8460x; 1.0149x over previous
#include <cuda_runtime.h>
#include <cuda_fp16.h>
#include <cstdint>
#include <math.h>

#define BQ 4096
#define SN 8192
#define DX 256
#define DY 128
#define BM 128
#define BN 128
#define BKC 64             // fp16 k per stage
#define NSPLIT 32
#define NTHREADS 256
#define NSTG 6             // 4 X stages + 2 Y stages per tile
#define NTILE ((SN/NSPLIT)/BN)  // 2
#define NSS (NTILE*NSTG)   // 12 B-stages per CTA
#define SROWB 144          // B smem row stride bytes (72 fp16)

// A resident: 128 rows x 384 fp16 (x|y concat), row stride 392 fp16 = 784 B
#define AROWB 784
#define A_BYTES (BM*AROWB)           // 100352
// B stages after A
#define OFF_B A_BYTES
#define BSTG_STRIDE 18432
#define SMEM_BYTES (A_BYTES + 3*BSTG_STRIDE)   // 155648

// ---------------- device scratch ----------------
__device__ __align__(16) __half g_xa[BQ*DX];
__device__ __align__(16) __half g_xb[SN*DX];
__device__ __align__(16) __half g_ya[BQ*DY];
__device__ __align__(16) __half g_yb[SN*DY];
__device__ float g_x2[BQ], g_y2[BQ], g_xs2[SN], g_ys2[SN];
__device__ float g_pm[3*BQ*NSPLIT], g_ps[3*BQ*NSPLIT];
__device__ float g_part[96];

// ---------------- helpers ----------------
__device__ __forceinline__ uint32_t smem_u32(const void* p) {
    uint32_t a;
    asm("{ .reg .u64 t; cvta.to.shared.u64 t, %1; cvt.u32.u64 %0, t; }" : "=r"(a) : "l"(p));
    return a;
}
__device__ __forceinline__ void cp16(uint32_t s, const void* g) {
    asm volatile("cp.async.cg.shared.global [%0], [%1], 16;" :: "r"(s), "l"(g));
}
__device__ __forceinline__ void cp_commit() { asm volatile("cp.async.commit_group;" ::: "memory"); }
__device__ __forceinline__ void cp_wait1()  { asm volatile("cp.async.wait_group 1;" ::: "memory"); }
__device__ __forceinline__ void cp_wait0()  { asm volatile("cp.async.wait_group 0;" ::: "memory"); }

__device__ __forceinline__ void ldm_x4(uint32_t* r, uint32_t addr) {
    asm volatile("ldmatrix.sync.aligned.m8n8.x4.shared.b16 {%0,%1,%2,%3}, [%4];"
        : "=r"(r[0]), "=r"(r[1]), "=r"(r[2]), "=r"(r[3]) : "r"(addr));
}

__device__ __forceinline__ void hmma(float* d, const uint32_t* a, const uint32_t* b) {
    asm volatile(
        "mma.sync.aligned.m16n8k16.row.col.f32.f16.f16.f32 "
        "{%0,%1,%2,%3}, {%4,%5,%6,%7}, {%8,%9}, {%0,%1,%2,%3};"
        : "+f"(d[0]), "+f"(d[1]), "+f"(d[2]), "+f"(d[3])
        : "r"(a[0]), "r"(a[1]), "r"(a[2]), "r"(a[3]), "r"(b[0]), "r"(b[1]));
}

// ---------------- fused prep (fp16 convert) + norms: one warp per row ----------------
__global__ void prep_norms(const float* __restrict__ x, const float* __restrict__ y,
                           const float* __restrict__ xs, const float* __restrict__ ys) {
    int warp = (blockIdx.x * blockDim.x + threadIdx.x) >> 5;
    int lane = threadIdx.x & 31;
    const float* src; int dim; float* ndst; __half* hdst; int row;
    if (warp < BQ)            { src = x;  dim = DX; ndst = g_x2;  hdst = g_xa; row = warp; }
    else if (warp < 2*BQ)     { src = y;  dim = DY; ndst = g_y2;  hdst = g_ya; row = warp - BQ; }
    else if (warp < 2*BQ+SN)  { src = xs; dim = DX; ndst = g_xs2; hdst = g_xb; row = warp - 2*BQ; }
    else                      { src = ys; dim = DY; ndst = g_ys2; hdst = g_yb; row = warp - 2*BQ - SN; }
    const float4* p = (const float4*)(src + (size_t)row * dim);
    uint2* hp = (uint2*)(hdst + (size_t)row * dim);
    float s = 0.f;
    for (int i = lane; i < dim/4; i += 32) {
        float4 v = p[i];
        s += v.x*v.x + v.y*v.y + v.z*v.z + v.w*v.w;
        __half2 h0 = __floats2half2_rn(v.x, v.y);
        __half2 h1 = __floats2half2_rn(v.z, v.w);
        hp[i] = make_uint2(*(const uint32_t*)&h0, *(const uint32_t*)&h1);
    }
    #pragma unroll
    for (int o = 16; o; o >>= 1) s += __shfl_xor_sync(0xffffffffu, s, o);
    if (lane == 0) ndst[row] = s;
}

// ---------------- A resident load: 128 rows x [x(256)|y(128)] fp16 ----------------
__device__ __forceinline__ void issue_a(uint32_t sb, int row0, int tid) {
    // 6144 float4 units: 48 per row (32 from x, 16 from y)
    #pragma unroll
    for (int i = 0; i < 24; i++) {
        int u = tid + i * NTHREADS;
        int r = u / 48, c = u % 48;
        const __half* src = (c < 32) ? (g_xa + (size_t)(row0 + r) * DX + c * 8)
                                     : (g_ya + (size_t)(row0 + r) * DY + (c - 32) * 8);
        cp16(sb + r * AROWB + c * 16, src);
    }
    cp_commit();
}

// ---------------- B stage load via cp.async; buf = ss % 3 ----------------
// 128 rows x 64 fp16 = 1024 float4 units = exactly 4 per thread.
__device__ __forceinline__ void issue_stage(uint32_t sb, int ss, int sc0, int tid) {
    const int tile = ss / NSTG, s = ss % NSTG;
    const int c0 = sc0 + tile * BN;
    const __half* bsrc; int ldk, kc;
    if (s < 4) { bsrc = g_xb + (size_t)c0 * DX; ldk = DX; kc = s * BKC; }
    else       { bsrc = g_yb + (size_t)c0 * DY; ldk = DY; kc = (s - 4) * BKC; }
    uint32_t base = sb + OFF_B + (ss % 3) * BSTG_STRIDE;
    #pragma unroll
    for (int i = 0; i < 4; i++) {
        int u = tid + i * NTHREADS;      // 0..1023
        int r = u >> 3, cv = u & 7;
        cp16(base + r * SROWB + cv * 16, bsrc + (size_t)r * ldk + kc + cv * 8);
    }
    cp_commit();
}

// ---------------- warp mma over one 64-k stage via ldmatrix ----------------
// aL: lane base into resident A (bytes); bL: lane base into B stage buffer.
__device__ __forceinline__ void mma_stage(uint32_t aL, uint32_t bL, int kbase,
                                          float (*d)[8][4]) {
    #pragma unroll
    for (int kk = 0; kk < 4; kk++) {
        uint32_t a[2][4], b[8][2];
        const uint32_t ka = (uint32_t)(kbase + kk * 16) * 2;
        #pragma unroll
        for (int mi = 0; mi < 2; mi++)
            ldm_x4(a[mi], aL + mi * 16 * AROWB + ka);
        #pragma unroll
        for (int n2 = 0; n2 < 4; n2++)
            ldm_x4(&b[n2*2][0], bL + n2 * 16 * SROWB + kk * 32);
        #pragma unroll
        for (int mi = 0; mi < 2; mi++)
            #pragma unroll
            for (int ni = 0; ni < 8; ni++)
                hmma(d[mi][ni], a[mi], b[ni]);
    }
}

extern __shared__ char dynsmem[];

__global__ __launch_bounds__(NTHREADS, 1)
void mi_mma() {
    const uint32_t sb = smem_u32(dynsmem);
    const int tid = threadIdx.x;
    const int wid = tid >> 5, lane = tid & 31;
    const int wm = wid & 3, wn = wid >> 2;
    const int g = lane >> 2, t = lane & 3;
    const int row0 = blockIdx.x * BM;
    const int split = blockIdx.y;
    const int sc0 = split * (SN / NSPLIT);

    // ldmatrix lane address bases
    const int rl = lane & 7, q1 = (lane >> 3) & 1, q2 = (lane >> 4) & 1;
    const uint32_t aL = sb + (uint32_t)(wm*32 + rl + q1*8) * AROWB + (uint32_t)(q2*16);
    const uint32_t bLbase = sb + OFF_B +
        (uint32_t)(wn*64 + rl + q2*8) * SROWB + (uint32_t)(q1*16);

    float bx4[4], by4[4];
    #pragma unroll
    for (int mi = 0; mi < 2; mi++)
        #pragma unroll
        for (int rh = 0; rh < 2; rh++) {
            int r = row0 + wm*32 + mi*16 + g + rh*8;
            bx4[mi*2+rh] = -0.5f * g_x2[r];
            by4[mi*2+rh] = -0.5f * g_y2[r];
        }

    // lm[2] implicit: mZ = mX + mY
    float lm[3][4], ls[3][4];
    #pragma unroll
    for (int tt = 0; tt < 3; tt++)
        #pragma unroll
        for (int r = 0; r < 4; r++) { lm[tt][r] = -1e30f; ls[tt][r] = 0.f; }

    issue_a(sb, row0, tid);          // group: A
    issue_stage(sb, 0, sc0, tid);    // group: s0
    issue_stage(sb, 1, sc0, tid);    // group: s1

    for (int t0 = 0; t0 < NTILE; t0++) {
        const int c0 = sc0 + t0 * BN;

        float dx[2][8][4], dy[2][8][4];
        #pragma unroll
        for (int mi = 0; mi < 2; mi++)
            #pragma unroll
            for (int ni = 0; ni < 8; ni++)
                #pragma unroll
                for (int k = 0; k < 4; k++) { dx[mi][ni][k] = 0.f; dy[mi][ni][k] = 0.f; }

        #pragma unroll
        for (int s = 0; s < NSTG; s++) {
            const int ss = t0 * NSTG + s;
            if (ss == NSS - 1) cp_wait0(); else cp_wait1();
            __syncthreads();                      // data ready + prev readers done
            if (ss + 2 < NSS) issue_stage(sb, ss + 2, sc0, tid);
            uint32_t bL = bLbase + (ss % 3) * BSTG_STRIDE;
            // A k-base: X stages s=0..3 -> 64s; Y stages s=4,5 -> 256+64(s-4) = 64s
            if (s < 4) mma_stage(aL, bL, s * BKC, dx);
            else       mma_stage(aL, bL, s * BKC, dy);
        }

        // ---- epilogue: fold D_x, D_y into online LSEs (next-tile cp.async in flight) ----
        float cxa[8][2], cya[8][2];
        #pragma unroll
        for (int ni = 0; ni < 8; ni++) {
            int col = c0 + wn*64 + ni*8 + 2*t;
            float2 vx = *(const float2*)&g_xs2[col];
            float2 vy = *(const float2*)&g_ys2[col];
            cxa[ni][0] = -0.5f * vx.x; cxa[ni][1] = -0.5f * vx.y;
            cya[ni][0] = -0.5f * vy.x; cya[ni][1] = -0.5f * vy.y;
        }
        #pragma unroll
        for (int mi = 0; mi < 2; mi++)
            #pragma unroll
            for (int ni = 0; ni < 8; ni++)
                #pragma unroll
                for (int rh = 0; rh < 2; rh++)
                    #pragma unroll
                    for (int cc = 0; cc < 2; cc++) {
                        const int rr = mi*2 + rh;
                        float ex = dx[mi][ni][rh*2+cc] + bx4[rr] + cxa[ni][cc];
                        float ey = dy[mi][ni][rh*2+cc] + by4[rr] + cya[ni][cc];
                        float dXv = ex - lm[0][rr];
                        float tX = __expf(-fabsf(dXv));
                        bool fX = dXv > 0.f;
                        ls[0][rr] = fX ? fmaf(ls[0][rr], tX, 1.f) : ls[0][rr] + tX;
                        lm[0][rr] = fX ? ex : lm[0][rr];
                        float u  = fX ? 1.f : tX;
                        float rx = fX ? tX : 1.f;
                        float dYv = ey - lm[1][rr];
                        float tY = __expf(-fabsf(dYv));
                        bool fY = dYv > 0.f;
                        ls[1][rr] = fY ? fmaf(ls[1][rr], tY, 1.f) : ls[1][rr] + tY;
                        lm[1][rr] = fY ? ey : lm[1][rr];
                        float v  = fY ? 1.f : tY;
                        float ry = fY ? tY : 1.f;
                        ls[2][rr] = fmaf(ls[2][rr], rx * ry, u * v);
                    }
    }

    // materialize mZ
    #pragma unroll
    for (int r = 0; r < 4; r++) lm[2][r] = lm[0][r] + lm[1][r];

    // ---- merge across the 4 't' lanes sharing each row ----
    #pragma unroll
    for (int tt = 0; tt < 3; tt++)
        #pragma unroll
        for (int r = 0; r < 4; r++) {
            float m = lm[tt][r], s = ls[tt][r];
            #pragma unroll
            for (int off = 1; off <= 2; off <<= 1) {
                float mo = __shfl_xor_sync(0xffffffffu, m, off);
                float so = __shfl_xor_sync(0xffffffffu, s, off);
                float M = fmaxf(m, mo);
                s = s * __expf(m - M) + so * __expf(mo - M);
                m = M;
            }
            lm[tt][r] = m; ls[tt][r] = s;
        }

    __syncthreads();
    float* red = (float*)dynsmem;   // [3][128][2][2] = 6 KB, aliases A (done)
    if (t == 0) {
        #pragma unroll
        for (int tt = 0; tt < 3; tt++)
            #pragma unroll
            for (int mi = 0; mi < 2; mi++)
                #pragma unroll
                for (int rh = 0; rh < 2; rh++) {
                    int rr = wm*32 + mi*16 + g + rh*8;
                    red[((tt*BM + rr)*2 + wn)*2 + 0] = lm[tt][mi*2+rh];
                    red[((tt*BM + rr)*2 + wn)*2 + 1] = ls[tt][mi*2+rh];
                }
    }
    __syncthreads();
    for (int task = tid; task < 3*BM; task += NTHREADS) {
        int tt = task >> 7, rr = task & 127;
        float m0 = red[((tt*BM + rr)*2 + 0)*2 + 0], s0 = red[((tt*BM + rr)*2 + 0)*2 + 1];
        float m1 = red[((tt*BM + rr)*2 + 1)*2 + 0], s1 = red[((tt*BM + rr)*2 + 1)*2 + 1];
        float M = fmaxf(m0, m1);
        float S = s0 * __expf(m0 - M) + s1 * __expf(m1 - M);
        int gidx = (tt*BQ + row0 + rr) * NSPLIT + split;
        g_pm[gidx] = M;
        g_ps[gidx] = S;
    }
}

// ---------------- finalize stage 1: 96 blocks, one (row,term) per thread ----------------
__global__ void finalize_part() {
    __shared__ float acc[128];
    int task = blockIdx.x * 128 + threadIdx.x;    // 0..12287 = tt*BQ + r
    int base = task * NSPLIT;
    const float4* pm4 = (const float4*)&g_pm[base];
    const float4* ps4 = (const float4*)&g_ps[base];
    float M = -1e30f;
    #pragma unroll
    for (int q = 0; q < NSPLIT/4; q++) {
        float4 v = pm4[q];
        M = fmaxf(M, fmaxf(fmaxf(v.x, v.y), fmaxf(v.z, v.w)));
    }
    float S = 0.f;
    #pragma unroll
    for (int q = 0; q < NSPLIT/4; q++) {
        float4 vm = pm4[q]; float4 vs = ps4[q];
        S += vs.x * __expf(vm.x - M) + vs.y * __expf(vm.y - M)
           + vs.z * __expf(vm.z - M) + vs.w * __expf(vm.w - M);
    }
    float lse = M + logf(S);
    int tt = task >> 12;                           // BQ = 4096
    acc[threadIdx.x] = (tt == 2) ? lse : -lse;
    __syncthreads();
    #pragma unroll
    for (int o = 64; o; o >>= 1) {
        if (threadIdx.x < o) acc[threadIdx.x] += acc[threadIdx.x + o];
        __syncthreads();
    }
    if (threadIdx.x == 0) g_part[blockIdx.x] = acc[0];
}

// ---------------- finalize stage 2 ----------------
__global__ void finalize2(float* __restrict__ out) {
    float v = (threadIdx.x < 96) ? g_part[threadIdx.x] : 0.f;
    #pragma unroll
    for (int o = 16; o; o >>= 1) v += __shfl_xor_sync(0xffffffffu, v, o);
    __shared__ float w[4];
    if ((threadIdx.x & 31) == 0) w[threadIdx.x >> 5] = v;
    __syncthreads();
    if (threadIdx.x == 0) out[0] = (w[0] + w[1] + w[2] + w[3]) / (float)BQ;
}

extern "C" void kernel_launch(void* const* d_in, const int* in_sizes, int n_in,
                              void* d_out, int out_size) {
    (void)in_sizes; (void)n_in; (void)out_size;
    const float* x  = (const float*)d_in[0];
    const float* y  = (const float*)d_in[1];
    const float* xs = (const float*)d_in[2];
    const float* ys = (const float*)d_in[3];

    cudaFuncSetAttribute(mi_mma, cudaFuncAttributeMaxDynamicSharedMemorySize, SMEM_BYTES);

    prep_norms<<<(2*BQ + 2*SN) / 8, 256>>>(x, y, xs, ys);

    dim3 grid(BQ / BM, NSPLIT);
    mi_mma<<<grid, NTHREADS, SMEM_BYTES>>>();

    finalize_part<<<96, 128>>>();
    finalize2<<<1, 128>>>((float*)d_out);
}